// round 14
// baseline (speedup 1.0000x reference)
#include <cuda_runtime.h>
#include <cuda_bf16.h>
#include <math.h>
#include <stdint.h>

#define BS_   2
#define S_    2048
#define D_    2048
#define DOWN_ 512
#define UP_   1024
#define H_    16
#define RD_   32
#define MROWS (BS_*S_)

#define INVSCALE (1.0f/16.970562748477139f)

// fp32 scratch
__device__ float g_qr [MROWS*(RD_*H_)];
__device__ float g_krl[MROWS*RD_];
// bf16 hi/lo planes
__device__ __nv_bfloat16 g_hH [MROWS*D_],      g_hL [MROWS*D_];
__device__ __nv_bfloat16 g_WdkvH[DOWN_*D_],    g_WdkvL[DOWN_*D_];
__device__ __nv_bfloat16 g_WdqH [DOWN_*D_],    g_WdqL [DOWN_*D_];
__device__ __nv_bfloat16 g_WukH [UP_*DOWN_],   g_WukL [UP_*DOWN_];
__device__ __nv_bfloat16 g_WuvH [UP_*DOWN_],   g_WuvL [UP_*DOWN_];
__device__ __nv_bfloat16 g_WuqH [UP_*DOWN_],   g_WuqL [UP_*DOWN_];
__device__ __nv_bfloat16 g_WqrH [RD_*H_*DOWN_],g_WqrL [RD_*H_*DOWN_];
__device__ __nv_bfloat16 g_WfcH [D_*UP_],      g_WfcL [D_*UP_];
__device__ __nv_bfloat16 g_ckvH[MROWS*DOWN_],  g_ckvL[MROWS*DOWN_];
__device__ __nv_bfloat16 g_cqH [MROWS*DOWN_],  g_cqL [MROWS*DOWN_];
__device__ __nv_bfloat16 g_kcH [MROWS*UP_],    g_kcL [MROWS*UP_];
__device__ __nv_bfloat16 g_vcH [MROWS*UP_],    g_vcL [MROWS*UP_];
__device__ __nv_bfloat16 g_qcH [MROWS*UP_],    g_qcL [MROWS*UP_];
__device__ __nv_bfloat16 g_qrH [MROWS*(RD_*H_)], g_qrL[MROWS*(RD_*H_)];
__device__ __nv_bfloat16 g_krlH[MROWS*RD_],    g_krlL[MROWS*RD_];
__device__ __nv_bfloat16 g_aoH [MROWS*UP_],    g_aoL [MROWS*UP_];

// ---------------- helpers ----------------
__device__ __forceinline__ void mma_bf16(float* d, const uint32_t* a,
                                         const uint32_t* b) {
    asm volatile(
        "mma.sync.aligned.m16n8k16.row.col.f32.bf16.bf16.f32 "
        "{%0,%1,%2,%3},{%4,%5,%6,%7},{%8,%9},{%0,%1,%2,%3};"
        : "+f"(d[0]), "+f"(d[1]), "+f"(d[2]), "+f"(d[3])
        : "r"(a[0]), "r"(a[1]), "r"(a[2]), "r"(a[3]), "r"(b[0]), "r"(b[1]));
}
__device__ __forceinline__ uint32_t bf2_as_u32(__nv_bfloat162 v) {
    return *reinterpret_cast<uint32_t*>(&v);
}
__device__ __forceinline__ float fexp(float x) {
    x = fmaxf(x, -87.0f);
    float t = x * 1.4426950408889634f;
    float n = rintf(t);
    float f = t - n;
    float p = 0.0013333558f;
    p = fmaf(p, f, 0.009618129f);
    p = fmaf(p, f, 0.0555041087f);
    p = fmaf(p, f, 0.2402265069f);
    p = fmaf(p, f, 0.6931471806f);
    p = fmaf(p, f, 1.0f);
    return p * __int_as_float(((int)n + 127) << 23);
}

// ---- split fp32 -> hi/lo bf16 planes (grid-stride, n % 4 == 0) ----
__global__ void split_kernel(const float* __restrict__ x,
                             __nv_bfloat16* __restrict__ hi,
                             __nv_bfloat16* __restrict__ lo, long n4)
{
    uint32_t* hu = (uint32_t*)hi;
    uint32_t* lu = (uint32_t*)lo;
    for (long i = blockIdx.x*(long)blockDim.x + threadIdx.x; i < n4;
         i += (long)gridDim.x*blockDim.x) {
        float4 v = ((const float4*)x)[i];
        __nv_bfloat162 h01 = __floats2bfloat162_rn(v.x, v.y);
        __nv_bfloat162 h23 = __floats2bfloat162_rn(v.z, v.w);
        float e0 = v.x - __low2float(h01), e1 = v.y - __high2float(h01);
        float e2 = v.z - __low2float(h23), e3 = v.w - __high2float(h23);
        hu[2*i]   = bf2_as_u32(h01);
        hu[2*i+1] = bf2_as_u32(h23);
        lu[2*i]   = bf2_as_u32(__floats2bfloat162_rn(e0, e1));
        lu[2*i+1] = bf2_as_u32(__floats2bfloat162_rn(e2, e3));
    }
}

// ---- tensor-core GEMM on pre-split planes (3xBF16) ----
// C = A @ B^T + bias. A,B given as hi/lo bf16 planes [rows][K].
// Output: fp32 C (if CH==nullptr) or hi/lo planes CH/CL.
#define PBK   20
#define PLANE (128*PBK)
__global__ void __launch_bounds__(256, 2) gemm_bf16p(
    const __nv_bfloat16* __restrict__ AH, const __nv_bfloat16* __restrict__ AL,
    const __nv_bfloat16* __restrict__ BH, const __nv_bfloat16* __restrict__ BL,
    const float* __restrict__ bias, float* __restrict__ C,
    __nv_bfloat16* __restrict__ CH, __nv_bfloat16* __restrict__ CL,
    int M, int N, int K)
{
    extern __shared__ uint32_t smu[];
    const int tid  = threadIdx.x;
    const int lane = tid & 31, warp = tid >> 5;
    const int wm = warp >> 2, wn = warp & 3;
    const int lr = lane >> 2, lc = lane & 3;
    const int rowBase = blockIdx.y*128, colBase = blockIdx.x*128;
    const int Ku = K >> 1;   // u32 per row
    const uint32_t* srcs[4] = {
        (const uint32_t*)AH + (size_t)rowBase*Ku,
        (const uint32_t*)AL + (size_t)rowBase*Ku,
        (const uint32_t*)BH + (size_t)colBase*Ku,
        (const uint32_t*)BL + (size_t)colBase*Ku };

    float acc[4][4][4];
    #pragma unroll
    for (int i = 0; i < 4; i++)
        #pragma unroll
        for (int j = 0; j < 4; j++)
            #pragma unroll
            for (int c = 0; c < 4; c++) acc[i][j][c] = 0.f;

    auto load_stage = [&](int st, int k0) {
        const int k0u = k0 >> 1;
        uint32_t* base = smu + st*4*PLANE;
        #pragma unroll
        for (int i = 0; i < 8; i++) {
            int q = tid + i*256;              // 2048 16B-chunks
            int plane = q >> 9, idx = q & 511;
            int row = idx >> 2, qd = idx & 3;
            uint4 v = *(const uint4*)(srcs[plane] + (size_t)row*Ku + k0u + qd*4);
            uint32_t* dst = base + plane*PLANE + row*PBK + qd*4;
            dst[0] = v.x; dst[1] = v.y; dst[2] = v.z; dst[3] = v.w;
        }
    };

    load_stage(0, 0);
    __syncthreads();

    const int nK = K >> 5;
    for (int t = 0; t < nK; t++) {
        const int cur = t & 1;
        if (t + 1 < nK) load_stage(cur ^ 1, (t + 1) << 5);

        const uint32_t* Ah = smu + cur*4*PLANE;
        #pragma unroll
        for (int s = 0; s < 2; s++) {
            const int colb = s*8;
            uint32_t ah[4][4], al[4][4];
            #pragma unroll
            for (int mi = 0; mi < 4; mi++) {
                const uint32_t* pa = Ah + (wm*64 + mi*16 + lr)*PBK + colb + lc;
                ah[mi][0] = pa[0];         ah[mi][2] = pa[4];
                ah[mi][1] = pa[8*PBK];     ah[mi][3] = pa[8*PBK + 4];
                const uint32_t* qa = pa + PLANE;
                al[mi][0] = qa[0];         al[mi][2] = qa[4];
                al[mi][1] = qa[8*PBK];     al[mi][3] = qa[8*PBK + 4];
            }
            #pragma unroll
            for (int ni = 0; ni < 4; ni++) {
                const uint32_t* pb = Ah + 2*PLANE + (wn*32 + ni*8 + lr)*PBK + colb + lc;
                uint32_t bh[2] = {pb[0], pb[4]};
                uint32_t bl[2] = {pb[PLANE], pb[PLANE + 4]};
                #pragma unroll
                for (int mi = 0; mi < 4; mi++) {
                    mma_bf16(acc[mi][ni], ah[mi], bh);
                    mma_bf16(acc[mi][ni], ah[mi], bl);
                    mma_bf16(acc[mi][ni], al[mi], bh);
                }
            }
        }
        __syncthreads();
    }

    const int Nu = N >> 1;
    #pragma unroll
    for (int mi = 0; mi < 4; mi++) {
        #pragma unroll
        for (int ni = 0; ni < 4; ni++) {
            int r0 = rowBase + wm*64 + mi*16 + lr;
            int c0 = colBase + wn*32 + ni*8 + lc*2;
            float2 bv = *(const float2*)&bias[c0];
            float v0 = acc[mi][ni][0] + bv.x, v1 = acc[mi][ni][1] + bv.y;
            float v2 = acc[mi][ni][2] + bv.x, v3 = acc[mi][ni][3] + bv.y;
            if (CH) {
                __nv_bfloat162 h01 = __floats2bfloat162_rn(v0, v1);
                __nv_bfloat162 h23 = __floats2bfloat162_rn(v2, v3);
                ((uint32_t*)CH)[(size_t)r0*Nu + (c0>>1)]     = bf2_as_u32(h01);
                ((uint32_t*)CH)[(size_t)(r0+8)*Nu + (c0>>1)] = bf2_as_u32(h23);
                ((uint32_t*)CL)[(size_t)r0*Nu + (c0>>1)] = bf2_as_u32(
                    __floats2bfloat162_rn(v0 - __low2float(h01), v1 - __high2float(h01)));
                ((uint32_t*)CL)[(size_t)(r0+8)*Nu + (c0>>1)] = bf2_as_u32(
                    __floats2bfloat162_rn(v2 - __low2float(h23), v3 - __high2float(h23)));
            } else {
                *(float2*)&C[(size_t)r0*N + c0]     = make_float2(v0, v1);
                *(float2*)&C[(size_t)(r0+8)*N + c0] = make_float2(v2, v3);
            }
        }
    }
}

// ---- small-N GEMM (for Wkr, N=32), fp32 ----
__global__ void __launch_bounds__(256) gemm_bias(
    const float* __restrict__ A, const float* __restrict__ Bw,
    const float* __restrict__ bias, float* __restrict__ C,
    int M, int N, int K)
{
    __shared__ float As[128][17];
    __shared__ float Bs[64][17];
    const int tid = threadIdx.x;
    const int ty = tid >> 3, tx = tid & 7;
    const int rowBase = blockIdx.y * 128, colBase = blockIdx.x * 64;
    float acc[4][8];
    #pragma unroll
    for (int i = 0; i < 4; i++)
        #pragma unroll
        for (int j = 0; j < 8; j++) acc[i][j] = 0.f;

    for (int k0 = 0; k0 < K; k0 += 16) {
        #pragma unroll
        for (int i = 0; i < 8; i++) {
            int lin = tid + i*256, r = lin >> 4, c = lin & 15;
            As[r][c] = A[(size_t)(rowBase + r)*K + k0 + c];
        }
        #pragma unroll
        for (int i = 0; i < 4; i++) {
            int lin = tid + i*256, r = lin >> 4, c = lin & 15;
            int gr = colBase + r;
            Bs[r][c] = (gr < N) ? Bw[(size_t)gr*K + k0 + c] : 0.f;
        }
        __syncthreads();
        #pragma unroll
        for (int kk = 0; kk < 16; kk++) {
            float a[4], b[8];
            #pragma unroll
            for (int i = 0; i < 4; i++) a[i] = As[ty*4 + i][kk];
            #pragma unroll
            for (int j = 0; j < 8; j++) b[j] = Bs[tx + 8*j][kk];
            #pragma unroll
            for (int i = 0; i < 4; i++)
                #pragma unroll
                for (int j = 0; j < 8; j++)
                    acc[i][j] = fmaf(a[i], b[j], acc[i][j]);
        }
        __syncthreads();
    }
    #pragma unroll
    for (int i = 0; i < 4; i++) {
        int r = rowBase + ty*4 + i;
        #pragma unroll
        for (int j = 0; j < 8; j++) {
            int cN = colBase + tx + 8*j;
            if (cN < N) C[(size_t)r*N + cN] = acc[i][j] + bias[cN];
        }
    }
}

// ---- RoPE (NEGATED angle), reads fp32, writes hi/lo planes ----
__global__ void rope_split(const float* __restrict__ src,
                           __nv_bfloat16* __restrict__ dh,
                           __nv_bfloat16* __restrict__ dl,
                           int nheads, int rowStride)
{
    int row = blockIdx.x;
    int pos = row & (S_ - 1);
    int t = threadIdx.x;
    if (t >= nheads*16) return;
    int hh = t >> 4, j = t & 15;
    size_t base = (size_t)row*rowStride + hh*32;
    double lf = -(double)j * (log(10000.0) / 16.0);
    float inv_freq = (float)exp(lf);
    float theta = (float)pos * inv_freq;
    float c, sn;
    sincosf(theta, &c, &sn);
    float x1 = src[base + j], x2 = src[base + j + 16];
    float y1 = x1*c + x2*sn;
    float y2 = x2*c - x1*sn;
    __nv_bfloat16 h1 = __float2bfloat16_rn(y1);
    __nv_bfloat16 h2 = __float2bfloat16_rn(y2);
    dh[base + j]      = h1;
    dh[base + j + 16] = h2;
    dl[base + j]      = __float2bfloat16_rn(y1 - __bfloat162float(h1));
    dl[base + j + 16] = __float2bfloat16_rn(y2 - __bfloat162float(h2));
}

// ---- Flash attention (causal) on mma.sync bf16x3, pre-split inputs ----
#define AP 52
#define VP 36
__global__ void __launch_bounds__(128) attn_mma(
    const __nv_bfloat16* __restrict__ qcH, const __nv_bfloat16* __restrict__ qcL,
    const __nv_bfloat16* __restrict__ qrH, const __nv_bfloat16* __restrict__ qrL,
    const __nv_bfloat16* __restrict__ kcH, const __nv_bfloat16* __restrict__ kcL,
    const __nv_bfloat16* __restrict__ krH, const __nv_bfloat16* __restrict__ krL,
    const __nv_bfloat16* __restrict__ vcH, const __nv_bfloat16* __restrict__ vcL,
    __nv_bfloat16* __restrict__ aoH, __nv_bfloat16* __restrict__ aoL)
{
    extern __shared__ uint32_t su[];
    uint32_t* Qhi = su;
    uint32_t* Qlo = Qhi + 64*AP;
    uint32_t* Khi = Qlo + 64*AP;
    uint32_t* Klo = Khi + 64*AP;
    uint32_t* Vhi = Klo + 64*AP;
    uint32_t* Vlo = Vhi + 64*VP;
    uint16_t* VhiH = (uint16_t*)Vhi;
    uint16_t* VloH = (uint16_t*)Vlo;

    const int tid = threadIdx.x;
    const int lane = tid & 31, warp = tid >> 5;
    const int lr = lane >> 2, lc = lane & 3;
    const int qb = blockIdx.x, h = blockIdx.y, b = blockIdx.z;
    const int qs = qb*64;
    const int rowOff = b*S_;

    const uint32_t* qcHu = (const uint32_t*)qcH;
    const uint32_t* qcLu = (const uint32_t*)qcL;
    const uint32_t* qrHu = (const uint32_t*)qrH;
    const uint32_t* qrLu = (const uint32_t*)qrL;
    const uint32_t* kcHu = (const uint32_t*)kcH;
    const uint32_t* kcLu = (const uint32_t*)kcL;
    const uint32_t* krHu = (const uint32_t*)krH;
    const uint32_t* krLu = (const uint32_t*)krL;
    const uint32_t* vcHu = (const uint32_t*)vcH;
    const uint32_t* vcLu = (const uint32_t*)vcL;

    // Q tile: 64 rows x 48 u32 (96 bf16)
    for (int t = tid; t < 64*12; t += 128) {
        int r = t / 12, w = t - (t/12)*12;
        size_t grow = (size_t)(rowOff + qs + r);
        uint4 vh, vl;
        if (w < 8) {
            const uint32_t* p = qcHu + grow*(UP_/2) + h*32 + w*4;
            vh = *(const uint4*)p;
            vl = *(const uint4*)(qcLu + grow*(UP_/2) + h*32 + w*4);
        } else {
            const uint32_t* p = qrHu + grow*(RD_*H_/2) + h*16 + (w-8)*4;
            vh = *(const uint4*)p;
            vl = *(const uint4*)(qrLu + grow*(RD_*H_/2) + h*16 + (w-8)*4);
        }
        uint32_t* dh = Qhi + r*AP + w*4;
        dh[0]=vh.x; dh[1]=vh.y; dh[2]=vh.z; dh[3]=vh.w;
        uint32_t* dl = Qlo + r*AP + w*4;
        dl[0]=vl.x; dl[1]=vl.y; dl[2]=vl.z; dl[3]=vl.w;
    }

    float m0 = -1e30f, m1 = -1e30f, l0s = 0.f, l1s = 0.f;
    float o[8][4];
    #pragma unroll
    for (int j = 0; j < 8; j++)
        #pragma unroll
        for (int c = 0; c < 4; c++) o[j][c] = 0.f;

    for (int kb = 0; kb <= qs; kb += 64) {
        __syncthreads();
        for (int t = tid; t < 64*12; t += 128) {
            int r = t / 12, w = t - (t/12)*12;
            size_t grow = (size_t)(rowOff + kb + r);
            uint4 vh, vl;
            if (w < 8) {
                vh = *(const uint4*)(kcHu + grow*(UP_/2) + h*32 + w*4);
                vl = *(const uint4*)(kcLu + grow*(UP_/2) + h*32 + w*4);
            } else {
                vh = *(const uint4*)(krHu + grow*(RD_/2) + (w-8)*4);
                vl = *(const uint4*)(krLu + grow*(RD_/2) + (w-8)*4);
            }
            uint32_t* dh = Khi + r*AP + w*4;
            dh[0]=vh.x; dh[1]=vh.y; dh[2]=vh.z; dh[3]=vh.w;
            uint32_t* dl = Klo + r*AP + w*4;
            dl[0]=vl.x; dl[1]=vl.y; dl[2]=vl.z; dl[3]=vl.w;
        }
        // V transposed [dim][key]
        for (int t = tid; t < 64*32; t += 128) {
            int r = t >> 5, j = t & 31;
            size_t grow = (size_t)(rowOff + kb + r);
            uint32_t vh = vcHu[grow*(UP_/2) + h*32 + j];
            uint32_t vl = vcLu[grow*(UP_/2) + h*32 + j];
            VhiH[(2*j)*(2*VP) + r]   = (uint16_t)(vh & 0xffff);
            VhiH[(2*j+1)*(2*VP) + r] = (uint16_t)(vh >> 16);
            VloH[(2*j)*(2*VP) + r]   = (uint16_t)(vl & 0xffff);
            VloH[(2*j+1)*(2*VP) + r] = (uint16_t)(vl >> 16);
        }
        __syncthreads();

        float s[8][4];
        #pragma unroll
        for (int j = 0; j < 8; j++)
            #pragma unroll
            for (int c = 0; c < 4; c++) s[j][c] = 0.f;

        const uint32_t* qh = Qhi + (warp*16 + lr)*AP + lc;
        const uint32_t* ql = Qlo + (warp*16 + lr)*AP + lc;
        #pragma unroll
        for (int t = 0; t < 6; t++) {
            uint32_t ah[4], al[4];
            const uint32_t* pq = qh + t*8;
            ah[0]=pq[0]; ah[1]=pq[8*AP]; ah[2]=pq[4]; ah[3]=pq[8*AP+4];
            const uint32_t* pl = ql + t*8;
            al[0]=pl[0]; al[1]=pl[8*AP]; al[2]=pl[4]; al[3]=pl[8*AP+4];
            #pragma unroll
            for (int j = 0; j < 8; j++) {
                const uint32_t* pk = Khi + (8*j + lr)*AP + t*8 + lc;
                uint32_t bh[2] = {pk[0], pk[4]};
                const uint32_t* kl = Klo + (8*j + lr)*AP + t*8 + lc;
                uint32_t bl[2] = {kl[0], kl[4]};
                mma_bf16(s[j], ah, bh);
                mma_bf16(s[j], ah, bl);
                mma_bf16(s[j], al, bh);
            }
        }

        const int row0 = qs + warp*16 + lr, row1 = row0 + 8;
        #pragma unroll
        for (int j = 0; j < 8; j++) {
            int c0 = kb + 8*j + 2*lc, c1 = c0 + 1;
            s[j][0] = (c0 > row0) ? -1e30f : s[j][0]*INVSCALE;
            s[j][1] = (c1 > row0) ? -1e30f : s[j][1]*INVSCALE;
            s[j][2] = (c0 > row1) ? -1e30f : s[j][2]*INVSCALE;
            s[j][3] = (c1 > row1) ? -1e30f : s[j][3]*INVSCALE;
        }

        float rm0 = -1e30f, rm1 = -1e30f;
        #pragma unroll
        for (int j = 0; j < 8; j++) {
            rm0 = fmaxf(rm0, fmaxf(s[j][0], s[j][1]));
            rm1 = fmaxf(rm1, fmaxf(s[j][2], s[j][3]));
        }
        rm0 = fmaxf(rm0, __shfl_xor_sync(0xffffffffu, rm0, 1));
        rm0 = fmaxf(rm0, __shfl_xor_sync(0xffffffffu, rm0, 2));
        rm1 = fmaxf(rm1, __shfl_xor_sync(0xffffffffu, rm1, 1));
        rm1 = fmaxf(rm1, __shfl_xor_sync(0xffffffffu, rm1, 2));
        float mn0 = fmaxf(m0, rm0), mn1 = fmaxf(m1, rm1);
        float cr0 = fexp(m0 - mn0), cr1 = fexp(m1 - mn1);
        l0s *= cr0; l1s *= cr1;
        #pragma unroll
        for (int j = 0; j < 8; j++) {
            o[j][0] *= cr0; o[j][1] *= cr0;
            o[j][2] *= cr1; o[j][3] *= cr1;
        }
        uint32_t phi[8][2], plo[8][2];
        float rs0 = 0.f, rs1 = 0.f;
        #pragma unroll
        for (int j = 0; j < 8; j++) {
            float p0 = fexp(s[j][0] - mn0), p1 = fexp(s[j][1] - mn0);
            float p2 = fexp(s[j][2] - mn1), p3 = fexp(s[j][3] - mn1);
            rs0 += p0 + p1; rs1 += p2 + p3;
            __nv_bfloat162 h01 = __floats2bfloat162_rn(p0, p1);
            __nv_bfloat162 h23 = __floats2bfloat162_rn(p2, p3);
            phi[j][0] = bf2_as_u32(h01);
            phi[j][1] = bf2_as_u32(h23);
            plo[j][0] = bf2_as_u32(__floats2bfloat162_rn(
                p0 - __low2float(h01), p1 - __high2float(h01)));
            plo[j][1] = bf2_as_u32(__floats2bfloat162_rn(
                p2 - __low2float(h23), p3 - __high2float(h23)));
        }
        rs0 += __shfl_xor_sync(0xffffffffu, rs0, 1);
        rs0 += __shfl_xor_sync(0xffffffffu, rs0, 2);
        rs1 += __shfl_xor_sync(0xffffffffu, rs1, 1);
        rs1 += __shfl_xor_sync(0xffffffffu, rs1, 2);
        l0s += rs0; l1s += rs1; m0 = mn0; m1 = mn1;

        #pragma unroll
        for (int t = 0; t < 4; t++) {
            uint32_t ah[4] = {phi[2*t][0], phi[2*t][1], phi[2*t+1][0], phi[2*t+1][1]};
            uint32_t al[4] = {plo[2*t][0], plo[2*t][1], plo[2*t+1][0], plo[2*t+1][1]};
            #pragma unroll
            for (int j = 0; j < 8; j++) {
                const uint32_t* pv = Vhi + (8*j + lr)*VP + t*8 + lc;
                uint32_t bh[2] = {pv[0], pv[4]};
                const uint32_t* pw = Vlo + (8*j + lr)*VP + t*8 + lc;
                uint32_t bl[2] = {pw[0], pw[4]};
                mma_bf16(o[j], ah, bh);
                mma_bf16(o[j], ah, bl);
                mma_bf16(o[j], al, bh);
            }
        }
    }

    // epilogue: write ao hi/lo planes
    float inv0 = 1.f / l0s, inv1 = 1.f / l1s;
    int grow0 = rowOff + qs + warp*16 + lr;
    uint32_t* aoHu = (uint32_t*)aoH;
    uint32_t* aoLu = (uint32_t*)aoL;
    #pragma unroll
    for (int j = 0; j < 8; j++) {
        int col = h*64 + 8*j + 2*lc;
        float v0 = o[j][0]*inv0, v1 = o[j][1]*inv0;
        float v2 = o[j][2]*inv1, v3 = o[j][3]*inv1;
        __nv_bfloat162 h01 = __floats2bfloat162_rn(v0, v1);
        __nv_bfloat162 h23 = __floats2bfloat162_rn(v2, v3);
        aoHu[(size_t)grow0*(UP_/2) + (col>>1)]     = bf2_as_u32(h01);
        aoHu[(size_t)(grow0+8)*(UP_/2) + (col>>1)] = bf2_as_u32(h23);
        aoLu[(size_t)grow0*(UP_/2) + (col>>1)] = bf2_as_u32(
            __floats2bfloat162_rn(v0 - __low2float(h01), v1 - __high2float(h01)));
        aoLu[(size_t)(grow0+8)*(UP_/2) + (col>>1)] = bf2_as_u32(
            __floats2bfloat162_rn(v2 - __low2float(h23), v3 - __high2float(h23)));
    }
}

extern "C" void kernel_launch(void* const* d_in, const int* in_sizes, int n_in,
                              void* d_out, int out_size)
{
    const float* h    = (const float*)d_in[0];
    const float* Wdkv = (const float*)d_in[2];  const float* bdkv = (const float*)d_in[3];
    const float* Wuk  = (const float*)d_in[4];  const float* buk  = (const float*)d_in[5];
    const float* Wuv  = (const float*)d_in[6];  const float* buv  = (const float*)d_in[7];
    const float* Wdq  = (const float*)d_in[8];  const float* bdq  = (const float*)d_in[9];
    const float* Wuq  = (const float*)d_in[10]; const float* buq  = (const float*)d_in[11];
    const float* Wqr  = (const float*)d_in[12]; const float* bqr  = (const float*)d_in[13];
    const float* Wkr  = (const float*)d_in[14]; const float* bkr  = (const float*)d_in[15];
    const float* Wfc  = (const float*)d_in[16]; const float* bfc  = (const float*)d_in[17];
    float* out = (float*)d_out;

    float *qr, *krl;
    cudaGetSymbolAddress((void**)&qr,  g_qr);
    cudaGetSymbolAddress((void**)&krl, g_krl);
    __nv_bfloat16 *hH,*hL,*WdkvH,*WdkvL,*WdqH,*WdqL,*WukH,*WukL,*WuvH,*WuvL,
        *WuqH,*WuqL,*WqrH,*WqrL,*WfcH,*WfcL,*ckvH,*ckvL,*cqH,*cqL,
        *kcH,*kcL,*vcH,*vcL,*qcH,*qcL,*qrH,*qrL,*krlH,*krlL,*aoH,*aoL;
    cudaGetSymbolAddress((void**)&hH, g_hH);     cudaGetSymbolAddress((void**)&hL, g_hL);
    cudaGetSymbolAddress((void**)&WdkvH, g_WdkvH); cudaGetSymbolAddress((void**)&WdkvL, g_WdkvL);
    cudaGetSymbolAddress((void**)&WdqH, g_WdqH); cudaGetSymbolAddress((void**)&WdqL, g_WdqL);
    cudaGetSymbolAddress((void**)&WukH, g_WukH); cudaGetSymbolAddress((void**)&WukL, g_WukL);
    cudaGetSymbolAddress((void**)&WuvH, g_WuvH); cudaGetSymbolAddress((void**)&WuvL, g_WuvL);
    cudaGetSymbolAddress((void**)&WuqH, g_WuqH); cudaGetSymbolAddress((void**)&WuqL, g_WuqL);
    cudaGetSymbolAddress((void**)&WqrH, g_WqrH); cudaGetSymbolAddress((void**)&WqrL, g_WqrL);
    cudaGetSymbolAddress((void**)&WfcH, g_WfcH); cudaGetSymbolAddress((void**)&WfcL, g_WfcL);
    cudaGetSymbolAddress((void**)&ckvH, g_ckvH); cudaGetSymbolAddress((void**)&ckvL, g_ckvL);
    cudaGetSymbolAddress((void**)&cqH, g_cqH);   cudaGetSymbolAddress((void**)&cqL, g_cqL);
    cudaGetSymbolAddress((void**)&kcH, g_kcH);   cudaGetSymbolAddress((void**)&kcL, g_kcL);
    cudaGetSymbolAddress((void**)&vcH, g_vcH);   cudaGetSymbolAddress((void**)&vcL, g_vcL);
    cudaGetSymbolAddress((void**)&qcH, g_qcH);   cudaGetSymbolAddress((void**)&qcL, g_qcL);
    cudaGetSymbolAddress((void**)&qrH, g_qrH);   cudaGetSymbolAddress((void**)&qrL, g_qrL);
    cudaGetSymbolAddress((void**)&krlH, g_krlH); cudaGetSymbolAddress((void**)&krlL, g_krlL);
    cudaGetSymbolAddress((void**)&aoH, g_aoH);   cudaGetSymbolAddress((void**)&aoL, g_aoL);

    const int ATT_SMEM  = (4*64*AP + 2*64*VP)*(int)sizeof(uint32_t);
    const int GEMM_SMEM = 2*4*PLANE*(int)sizeof(uint32_t);
    cudaFuncSetAttribute(attn_mma,
                         cudaFuncAttributeMaxDynamicSharedMemorySize, ATT_SMEM);
    cudaFuncSetAttribute(gemm_bf16p,
                         cudaFuncAttributeMaxDynamicSharedMemorySize, GEMM_SMEM);

    // 1. split inputs into hi/lo bf16 planes
    split_kernel<<<1024, 256>>>(h,    hH,    hL,    (long)MROWS*D_/4);
    split_kernel<<<512,  256>>>(Wdkv, WdkvH, WdkvL, (long)DOWN_*D_/4);
    split_kernel<<<512,  256>>>(Wdq,  WdqH,  WdqL,  (long)DOWN_*D_/4);
    split_kernel<<<256,  256>>>(Wuk,  WukH,  WukL,  (long)UP_*DOWN_/4);
    split_kernel<<<256,  256>>>(Wuv,  WuvH,  WuvL,  (long)UP_*DOWN_/4);
    split_kernel<<<256,  256>>>(Wuq,  WuqH,  WuqL,  (long)UP_*DOWN_/4);
    split_kernel<<<128,  256>>>(Wqr,  WqrH,  WqrL,  (long)RD_*H_*DOWN_/4);
    split_kernel<<<1024, 256>>>(Wfc,  WfcH,  WfcL,  (long)D_*UP_/4);

    // 2. projections (planes in, planes/fp32 out)
    gemm_bf16p<<<dim3(DOWN_/128, MROWS/128), 256, GEMM_SMEM>>>(
        hH, hL, WdkvH, WdkvL, bdkv, nullptr, ckvH, ckvL, MROWS, DOWN_, D_);
    gemm_bf16p<<<dim3(DOWN_/128, MROWS/128), 256, GEMM_SMEM>>>(
        hH, hL, WdqH, WdqL, bdq, nullptr, cqH, cqL, MROWS, DOWN_, D_);
    gemm_bias<<<dim3(1, MROWS/128), 256>>>(h, Wkr, bkr, krl, MROWS, RD_, D_);
    gemm_bf16p<<<dim3(UP_/128, MROWS/128), 256, GEMM_SMEM>>>(
        ckvH, ckvL, WukH, WukL, buk, nullptr, kcH, kcL, MROWS, UP_, DOWN_);
    gemm_bf16p<<<dim3(UP_/128, MROWS/128), 256, GEMM_SMEM>>>(
        ckvH, ckvL, WuvH, WuvL, buv, nullptr, vcH, vcL, MROWS, UP_, DOWN_);
    gemm_bf16p<<<dim3(UP_/128, MROWS/128), 256, GEMM_SMEM>>>(
        cqH, cqL, WuqH, WuqL, buq, nullptr, qcH, qcL, MROWS, UP_, DOWN_);
    gemm_bf16p<<<dim3((RD_*H_)/128, MROWS/128), 256, GEMM_SMEM>>>(
        cqH, cqL, WqrH, WqrL, bqr, qr, nullptr, nullptr, MROWS, RD_*H_, DOWN_);

    // 3. RoPE (negated angle) -> planes
    rope_split<<<MROWS, 256>>>(qr,  qrH,  qrL,  H_, RD_*H_);
    rope_split<<<MROWS, 32>>>(krl, krlH, krlL, 1,  RD_);

    // 4. fused causal flash attention (planes in, planes out)
    attn_mma<<<dim3(S_/64, H_, BS_), 128, ATT_SMEM>>>(
        qcH, qcL, qrH, qrL, kcH, kcL, krlH, krlL, vcH, vcL, aoH, aoL);

    // 5. output projection (fp32 out)
    gemm_bf16p<<<dim3(D_/128, MROWS/128), 256, GEMM_SMEM>>>(
        aoH, aoL, WfcH, WfcL, bfc, out, nullptr, nullptr, MROWS, D_, UP_);
}

// round 15
// speedup vs baseline: 1.1414x; 1.1414x over previous
#include <cuda_runtime.h>
#include <cuda_bf16.h>
#include <math.h>
#include <stdint.h>

#define BS_   2
#define S_    2048
#define D_    2048
#define DOWN_ 512
#define UP_   1024
#define H_    16
#define RD_   32
#define MROWS (BS_*S_)

#define INVSCALE (1.0f/16.970562748477139f)

__device__ float g_ckv[MROWS*DOWN_];
__device__ float g_cq [MROWS*DOWN_];
__device__ float g_krl[MROWS*RD_];
__device__ float g_kc [MROWS*UP_];
__device__ float g_vc [MROWS*UP_];
__device__ float g_qc [MROWS*UP_];
__device__ float g_qr [MROWS*(RD_*H_)];
__device__ float g_ao [MROWS*UP_];

// ---------------- bf16 helpers ----------------
__device__ __forceinline__ void mma_bf16(float* d, const uint32_t* a,
                                         const uint32_t* b) {
    asm volatile(
        "mma.sync.aligned.m16n8k16.row.col.f32.bf16.bf16.f32 "
        "{%0,%1,%2,%3},{%4,%5,%6,%7},{%8,%9},{%0,%1,%2,%3};"
        : "+f"(d[0]), "+f"(d[1]), "+f"(d[2]), "+f"(d[3])
        : "r"(a[0]), "r"(a[1]), "r"(a[2]), "r"(a[3]), "r"(b[0]), "r"(b[1]));
}
__device__ __forceinline__ uint32_t bf2_as_u32(__nv_bfloat162 v) {
    return *reinterpret_cast<uint32_t*>(&v);
}
__device__ __forceinline__ float fexp(float x) {
    x = fmaxf(x, -87.0f);
    float t = x * 1.4426950408889634f;
    float n = rintf(t);
    float f = t - n;
    float p = 0.0013333558f;
    p = fmaf(p, f, 0.009618129f);
    p = fmaf(p, f, 0.0555041087f);
    p = fmaf(p, f, 0.2402265069f);
    p = fmaf(p, f, 0.6931471806f);
    p = fmaf(p, f, 1.0f);
    return p * __int_as_float(((int)n + 127) << 23);
}

// ---- batched tensor-core GEMM (3xBF16, split-at-load like R13) ----
struct GJob { const float* A; const float* Bw; const float* bias; float* C;
              int N; int K; int nx; };
struct GJobs { GJob j[4]; };

#define PBK   20
#define PLANE (128*PBK)
__global__ void __launch_bounds__(256, 1) gemm_batch(GJobs jobs)
{
    extern __shared__ uint32_t smu[];
    const GJob job = jobs.j[blockIdx.z];
    if ((int)blockIdx.x >= job.nx) return;
    const int N = job.N, K = job.K;
    const float* __restrict__ A  = job.A;
    const float* __restrict__ Bw = job.Bw;

    const int tid  = threadIdx.x;
    const int lane = tid & 31, warp = tid >> 5;
    const int wm = warp >> 2, wn = warp & 3;
    const int lr = lane >> 2, lc = lane & 3;
    const int rowBase = blockIdx.y*128, colBase = blockIdx.x*128;
    const float* Ag = A  + (size_t)rowBase*K;
    const float* Bg = Bw + (size_t)colBase*K;

    float acc[4][4][4];
    #pragma unroll
    for (int i = 0; i < 4; i++)
        #pragma unroll
        for (int j = 0; j < 4; j++)
            #pragma unroll
            for (int c = 0; c < 4; c++) acc[i][j][c] = 0.f;

    auto load_stage = [&](int st, int k0) {
        uint32_t* base = smu + st*4*PLANE;
        #pragma unroll
        for (int i = 0; i < 4; i++) {
            int q = tid + i*256;
            int row = q >> 3, kq = (q & 7)*4;
            int col = kq >> 1;
            uint32_t* dst = base + row*PBK + col;
            float4 va = *(const float4*)(Ag + (size_t)row*K + k0 + kq);
            __nv_bfloat162 h01 = __floats2bfloat162_rn(va.x, va.y);
            __nv_bfloat162 h23 = __floats2bfloat162_rn(va.z, va.w);
            float l0 = va.x - __low2float(h01), l1 = va.y - __high2float(h01);
            float l2 = va.z - __low2float(h23), l3 = va.w - __high2float(h23);
            dst[0] = bf2_as_u32(h01); dst[1] = bf2_as_u32(h23);
            dst[PLANE+0] = bf2_as_u32(__floats2bfloat162_rn(l0, l1));
            dst[PLANE+1] = bf2_as_u32(__floats2bfloat162_rn(l2, l3));
            float4 vb = *(const float4*)(Bg + (size_t)row*K + k0 + kq);
            __nv_bfloat162 g01 = __floats2bfloat162_rn(vb.x, vb.y);
            __nv_bfloat162 g23 = __floats2bfloat162_rn(vb.z, vb.w);
            float m0 = vb.x - __low2float(g01), m1 = vb.y - __high2float(g01);
            float m2 = vb.z - __low2float(g23), m3 = vb.w - __high2float(g23);
            dst[2*PLANE+0] = bf2_as_u32(g01); dst[2*PLANE+1] = bf2_as_u32(g23);
            dst[3*PLANE+0] = bf2_as_u32(__floats2bfloat162_rn(m0, m1));
            dst[3*PLANE+1] = bf2_as_u32(__floats2bfloat162_rn(m2, m3));
        }
    };

    load_stage(0, 0);
    __syncthreads();

    const int nK = K >> 5;
    for (int t = 0; t < nK; t++) {
        const int cur = t & 1;
        if (t + 1 < nK) load_stage(cur ^ 1, (t + 1) << 5);

        const uint32_t* Ah = smu + cur*4*PLANE;
        #pragma unroll
        for (int s = 0; s < 2; s++) {
            const int colb = s*8;
            uint32_t ah[4][4], al[4][4];
            #pragma unroll
            for (int mi = 0; mi < 4; mi++) {
                const uint32_t* pa = Ah + (wm*64 + mi*16 + lr)*PBK + colb + lc;
                ah[mi][0] = pa[0];         ah[mi][2] = pa[4];
                ah[mi][1] = pa[8*PBK];     ah[mi][3] = pa[8*PBK + 4];
                const uint32_t* qa = pa + PLANE;
                al[mi][0] = qa[0];         al[mi][2] = qa[4];
                al[mi][1] = qa[8*PBK];     al[mi][3] = qa[8*PBK + 4];
            }
            #pragma unroll
            for (int ni = 0; ni < 4; ni++) {
                const uint32_t* pb = Ah + 2*PLANE + (wn*32 + ni*8 + lr)*PBK + colb + lc;
                uint32_t bh[2] = {pb[0], pb[4]};
                uint32_t bl[2] = {pb[PLANE], pb[PLANE + 4]};
                #pragma unroll
                for (int mi = 0; mi < 4; mi++) {
                    mma_bf16(acc[mi][ni], ah[mi], bh);
                    mma_bf16(acc[mi][ni], ah[mi], bl);
                    mma_bf16(acc[mi][ni], al[mi], bh);
                }
            }
        }
        __syncthreads();
    }

    float* C = job.C;
    const float* bias = job.bias;
    #pragma unroll
    for (int mi = 0; mi < 4; mi++) {
        #pragma unroll
        for (int ni = 0; ni < 4; ni++) {
            int r0 = rowBase + wm*64 + mi*16 + lr;
            int c0 = colBase + wn*32 + ni*8 + lc*2;
            float2 bv = *(const float2*)&bias[c0];
            float2 v0 = {acc[mi][ni][0] + bv.x, acc[mi][ni][1] + bv.y};
            float2 v1 = {acc[mi][ni][2] + bv.x, acc[mi][ni][3] + bv.y};
            *(float2*)&C[(size_t)r0*N + c0]       = v0;
            *(float2*)&C[(size_t)(r0 + 8)*N + c0] = v1;
        }
    }
}

// ---- small-N GEMM (for Wkr, N=32), fp32 ----
__global__ void __launch_bounds__(256) gemm_bias(
    const float* __restrict__ A, const float* __restrict__ Bw,
    const float* __restrict__ bias, float* __restrict__ C,
    int M, int N, int K)
{
    __shared__ float As[128][17];
    __shared__ float Bs[64][17];
    const int tid = threadIdx.x;
    const int ty = tid >> 3, tx = tid & 7;
    const int rowBase = blockIdx.y * 128, colBase = blockIdx.x * 64;
    float acc[4][8];
    #pragma unroll
    for (int i = 0; i < 4; i++)
        #pragma unroll
        for (int j = 0; j < 8; j++) acc[i][j] = 0.f;

    for (int k0 = 0; k0 < K; k0 += 16) {
        #pragma unroll
        for (int i = 0; i < 8; i++) {
            int lin = tid + i*256, r = lin >> 4, c = lin & 15;
            As[r][c] = A[(size_t)(rowBase + r)*K + k0 + c];
        }
        #pragma unroll
        for (int i = 0; i < 4; i++) {
            int lin = tid + i*256, r = lin >> 4, c = lin & 15;
            int gr = colBase + r;
            Bs[r][c] = (gr < N) ? Bw[(size_t)gr*K + k0 + c] : 0.f;
        }
        __syncthreads();
        #pragma unroll
        for (int kk = 0; kk < 16; kk++) {
            float a[4], b[8];
            #pragma unroll
            for (int i = 0; i < 4; i++) a[i] = As[ty*4 + i][kk];
            #pragma unroll
            for (int j = 0; j < 8; j++) b[j] = Bs[tx + 8*j][kk];
            #pragma unroll
            for (int i = 0; i < 4; i++)
                #pragma unroll
                for (int j = 0; j < 8; j++)
                    acc[i][j] = fmaf(a[i], b[j], acc[i][j]);
        }
        __syncthreads();
    }
    #pragma unroll
    for (int i = 0; i < 4; i++) {
        int r = rowBase + ty*4 + i;
        #pragma unroll
        for (int j = 0; j < 8; j++) {
            int cN = colBase + tx + 8*j;
            if (cN < N) C[(size_t)r*N + cN] = acc[i][j] + bias[cN];
        }
    }
}

// ---- RoPE in place, head_dim 32, NEGATED angle (matches reference) ----
__global__ void rope_kernel(float* __restrict__ x, int nheads, int rowStride)
{
    int row = blockIdx.x;
    int pos = row & (S_ - 1);
    int t = threadIdx.x;
    if (t >= nheads*16) return;
    int hh = t >> 4, j = t & 15;
    float* p = x + (size_t)row*rowStride + hh*32;
    double lf = -(double)j * (log(10000.0) / 16.0);
    float inv_freq = (float)exp(lf);
    float theta = (float)pos * inv_freq;
    float c, sn;
    sincosf(theta, &c, &sn);
    float x1 = p[j], x2 = p[j + 16];
    p[j]      = x1*c + x2*sn;
    p[j + 16] = x2*c - x1*sn;
}

// ---- Flash attention (causal), mma bf16x3, BM=128 (8 warps) ----
#define AP 52
#define VP 36
__global__ void __launch_bounds__(256) attn_mma(
    const float* __restrict__ qc, const float* __restrict__ qrr,
    const float* __restrict__ kc, const float* __restrict__ krr,
    const float* __restrict__ vc, float* __restrict__ out)
{
    extern __shared__ uint32_t su[];
    uint32_t* Qhi = su;                  // [128][AP]
    uint32_t* Qlo = Qhi + 128*AP;
    uint32_t* Khi = Qlo + 128*AP;        // [64][AP]
    uint32_t* Klo = Khi + 64*AP;
    uint32_t* Vhi = Klo + 64*AP;         // [64 dims][VP]
    uint32_t* Vlo = Vhi + 64*VP;
    uint16_t* VhiH = (uint16_t*)Vhi;
    uint16_t* VloH = (uint16_t*)Vlo;

    const int tid = threadIdx.x;
    const int lane = tid & 31, warp = tid >> 5;    // 8 warps
    const int lr = lane >> 2, lc = lane & 3;
    const int qb = blockIdx.x, h = blockIdx.y, b = blockIdx.z;
    const int qs = qb*128;
    const int rowOff = b*S_;

    // Q tile: 128 rows x 96 dims, split hi/lo
    for (int t = tid; t < 128*24; t += 256) {
        int r = t / 24, w = t - (t/24)*24;
        int grow = rowOff + qs + r;
        float4 v = (w < 16)
            ? *(const float4*)(qc  + (size_t)grow*UP_      + h*64 + 4*w)
            : *(const float4*)(qrr + (size_t)grow*(RD_*H_) + h*32 + 4*(w-16));
        __nv_bfloat162 h01 = __floats2bfloat162_rn(v.x, v.y);
        __nv_bfloat162 h23 = __floats2bfloat162_rn(v.z, v.w);
        float e0 = v.x - __low2float(h01), e1 = v.y - __high2float(h01);
        float e2 = v.z - __low2float(h23), e3 = v.w - __high2float(h23);
        Qhi[r*AP + 2*w]   = bf2_as_u32(h01);
        Qhi[r*AP + 2*w+1] = bf2_as_u32(h23);
        Qlo[r*AP + 2*w]   = bf2_as_u32(__floats2bfloat162_rn(e0, e1));
        Qlo[r*AP + 2*w+1] = bf2_as_u32(__floats2bfloat162_rn(e2, e3));
    }

    float m0 = -1e30f, m1 = -1e30f, l0s = 0.f, l1s = 0.f;
    float o[8][4];
    #pragma unroll
    for (int j = 0; j < 8; j++)
        #pragma unroll
        for (int c = 0; c < 4; c++) o[j][c] = 0.f;

    for (int kb = 0; kb <= qs + 64; kb += 64) {
        __syncthreads();
        // K tile split hi/lo (64 keys)
        for (int t = tid; t < 64*24; t += 256) {
            int r = t / 24, w = t - (t/24)*24;
            int grow = rowOff + kb + r;
            float4 v = (w < 16)
                ? *(const float4*)(kc  + (size_t)grow*UP_ + h*64 + 4*w)
                : *(const float4*)(krr + (size_t)grow*RD_ + 4*(w-16));
            __nv_bfloat162 h01 = __floats2bfloat162_rn(v.x, v.y);
            __nv_bfloat162 h23 = __floats2bfloat162_rn(v.z, v.w);
            float e0 = v.x - __low2float(h01), e1 = v.y - __high2float(h01);
            float e2 = v.z - __low2float(h23), e3 = v.w - __high2float(h23);
            Khi[r*AP + 2*w]   = bf2_as_u32(h01);
            Khi[r*AP + 2*w+1] = bf2_as_u32(h23);
            Klo[r*AP + 2*w]   = bf2_as_u32(__floats2bfloat162_rn(e0, e1));
            Klo[r*AP + 2*w+1] = bf2_as_u32(__floats2bfloat162_rn(e2, e3));
        }
        // V tile transposed [dim][key], split hi/lo
        for (int t = tid; t < 64*16; t += 256) {
            int r = t / 16, dq = t - (t/16)*16;
            int grow = rowOff + kb + r;
            float4 v = *(const float4*)(vc + (size_t)grow*UP_ + h*64 + 4*dq);
            float vv[4] = {v.x, v.y, v.z, v.w};
            #pragma unroll
            for (int e = 0; e < 4; e++) {
                int d = 4*dq + e;
                __nv_bfloat16 hb = __float2bfloat16_rn(vv[e]);
                float rem = vv[e] - __bfloat162float(hb);
                __nv_bfloat16 lb = __float2bfloat16_rn(rem);
                VhiH[d*(2*VP) + r] = *(uint16_t*)&hb;
                VloH[d*(2*VP) + r] = *(uint16_t*)&lb;
            }
        }
        __syncthreads();

        // S = Q K^T (3xBF16)
        float s[8][4];
        #pragma unroll
        for (int j = 0; j < 8; j++)
            #pragma unroll
            for (int c = 0; c < 4; c++) s[j][c] = 0.f;

        const uint32_t* qh = Qhi + (warp*16 + lr)*AP + lc;
        const uint32_t* ql = Qlo + (warp*16 + lr)*AP + lc;
        #pragma unroll
        for (int t = 0; t < 6; t++) {
            uint32_t ah[4], al[4];
            const uint32_t* pq = qh + t*8;
            ah[0]=pq[0]; ah[1]=pq[8*AP]; ah[2]=pq[4]; ah[3]=pq[8*AP+4];
            const uint32_t* pl = ql + t*8;
            al[0]=pl[0]; al[1]=pl[8*AP]; al[2]=pl[4]; al[3]=pl[8*AP+4];
            #pragma unroll
            for (int j = 0; j < 8; j++) {
                const uint32_t* pk = Khi + (8*j + lr)*AP + t*8 + lc;
                uint32_t bh[2] = {pk[0], pk[4]};
                const uint32_t* kl = Klo + (8*j + lr)*AP + t*8 + lc;
                uint32_t bl[2] = {kl[0], kl[4]};
                mma_bf16(s[j], ah, bh);
                mma_bf16(s[j], ah, bl);
                mma_bf16(s[j], al, bh);
            }
        }

        const int row0 = qs + warp*16 + lr, row1 = row0 + 8;
        #pragma unroll
        for (int j = 0; j < 8; j++) {
            int c0 = kb + 8*j + 2*lc, c1 = c0 + 1;
            s[j][0] = (c0 > row0) ? -1e30f : s[j][0]*INVSCALE;
            s[j][1] = (c1 > row0) ? -1e30f : s[j][1]*INVSCALE;
            s[j][2] = (c0 > row1) ? -1e30f : s[j][2]*INVSCALE;
            s[j][3] = (c1 > row1) ? -1e30f : s[j][3]*INVSCALE;
        }

        float rm0 = -1e30f, rm1 = -1e30f;
        #pragma unroll
        for (int j = 0; j < 8; j++) {
            rm0 = fmaxf(rm0, fmaxf(s[j][0], s[j][1]));
            rm1 = fmaxf(rm1, fmaxf(s[j][2], s[j][3]));
        }
        rm0 = fmaxf(rm0, __shfl_xor_sync(0xffffffffu, rm0, 1));
        rm0 = fmaxf(rm0, __shfl_xor_sync(0xffffffffu, rm0, 2));
        rm1 = fmaxf(rm1, __shfl_xor_sync(0xffffffffu, rm1, 1));
        rm1 = fmaxf(rm1, __shfl_xor_sync(0xffffffffu, rm1, 2));
        float mn0 = fmaxf(m0, rm0), mn1 = fmaxf(m1, rm1);
        float cr0 = fexp(m0 - mn0), cr1 = fexp(m1 - mn1);
        l0s *= cr0; l1s *= cr1;
        #pragma unroll
        for (int j = 0; j < 8; j++) {
            o[j][0] *= cr0; o[j][1] *= cr0;
            o[j][2] *= cr1; o[j][3] *= cr1;
        }
        uint32_t phi[8][2], plo[8][2];
        float rs0 = 0.f, rs1 = 0.f;
        #pragma unroll
        for (int j = 0; j < 8; j++) {
            float p0 = fexp(s[j][0] - mn0), p1 = fexp(s[j][1] - mn0);
            float p2 = fexp(s[j][2] - mn1), p3 = fexp(s[j][3] - mn1);
            rs0 += p0 + p1; rs1 += p2 + p3;
            __nv_bfloat162 h01 = __floats2bfloat162_rn(p0, p1);
            __nv_bfloat162 h23 = __floats2bfloat162_rn(p2, p3);
            phi[j][0] = bf2_as_u32(h01);
            phi[j][1] = bf2_as_u32(h23);
            plo[j][0] = bf2_as_u32(__floats2bfloat162_rn(
                p0 - __low2float(h01), p1 - __high2float(h01)));
            plo[j][1] = bf2_as_u32(__floats2bfloat162_rn(
                p2 - __low2float(h23), p3 - __high2float(h23)));
        }
        rs0 += __shfl_xor_sync(0xffffffffu, rs0, 1);
        rs0 += __shfl_xor_sync(0xffffffffu, rs0, 2);
        rs1 += __shfl_xor_sync(0xffffffffu, rs1, 1);
        rs1 += __shfl_xor_sync(0xffffffffu, rs1, 2);
        l0s += rs0; l1s += rs1; m0 = mn0; m1 = mn1;

        #pragma unroll
        for (int t = 0; t < 4; t++) {
            uint32_t ah[4] = {phi[2*t][0], phi[2*t][1], phi[2*t+1][0], phi[2*t+1][1]};
            uint32_t al[4] = {plo[2*t][0], plo[2*t][1], plo[2*t+1][0], plo[2*t+1][1]};
            #pragma unroll
            for (int j = 0; j < 8; j++) {
                const uint32_t* pv = Vhi + (8*j + lr)*VP + t*8 + lc;
                uint32_t bh[2] = {pv[0], pv[4]};
                const uint32_t* pw = Vlo + (8*j + lr)*VP + t*8 + lc;
                uint32_t bl[2] = {pw[0], pw[4]};
                mma_bf16(o[j], ah, bh);
                mma_bf16(o[j], ah, bl);
                mma_bf16(o[j], al, bh);
            }
        }
    }

    float inv0 = 1.f / l0s, inv1 = 1.f / l1s;
    int grow0 = rowOff + qs + warp*16 + lr;
    #pragma unroll
    for (int j = 0; j < 8; j++) {
        int col = h*64 + 8*j + 2*lc;
        float2 v0 = {o[j][0]*inv0, o[j][1]*inv0};
        float2 v1 = {o[j][2]*inv1, o[j][3]*inv1};
        *(float2*)&out[(size_t)grow0*UP_ + col]     = v0;
        *(float2*)&out[(size_t)(grow0+8)*UP_ + col] = v1;
    }
}

extern "C" void kernel_launch(void* const* d_in, const int* in_sizes, int n_in,
                              void* d_out, int out_size)
{
    const float* h    = (const float*)d_in[0];
    const float* Wdkv = (const float*)d_in[2];  const float* bdkv = (const float*)d_in[3];
    const float* Wuk  = (const float*)d_in[4];  const float* buk  = (const float*)d_in[5];
    const float* Wuv  = (const float*)d_in[6];  const float* buv  = (const float*)d_in[7];
    const float* Wdq  = (const float*)d_in[8];  const float* bdq  = (const float*)d_in[9];
    const float* Wuq  = (const float*)d_in[10]; const float* buq  = (const float*)d_in[11];
    const float* Wqr  = (const float*)d_in[12]; const float* bqr  = (const float*)d_in[13];
    const float* Wkr  = (const float*)d_in[14]; const float* bkr  = (const float*)d_in[15];
    const float* Wfc  = (const float*)d_in[16]; const float* bfc  = (const float*)d_in[17];
    float* out = (float*)d_out;

    float *ckv, *cq, *krl, *kc, *vc, *qc, *qr, *ao;
    cudaGetSymbolAddress((void**)&ckv, g_ckv);
    cudaGetSymbolAddress((void**)&cq,  g_cq);
    cudaGetSymbolAddress((void**)&krl, g_krl);
    cudaGetSymbolAddress((void**)&kc,  g_kc);
    cudaGetSymbolAddress((void**)&vc,  g_vc);
    cudaGetSymbolAddress((void**)&qc,  g_qc);
    cudaGetSymbolAddress((void**)&qr,  g_qr);
    cudaGetSymbolAddress((void**)&ao,  g_ao);

    const int ATT_SMEM  = (2*128*AP + 2*64*AP + 2*64*VP)*(int)sizeof(uint32_t); // 98304
    const int GEMM_SMEM = 2*4*PLANE*(int)sizeof(uint32_t);                      // 81920
    cudaFuncSetAttribute(attn_mma,
                         cudaFuncAttributeMaxDynamicSharedMemorySize, ATT_SMEM);
    cudaFuncSetAttribute(gemm_batch,
                         cudaFuncAttributeMaxDynamicSharedMemorySize, GEMM_SMEM);

    // stage 1: ckv + cq (both read h) in one launch
    {
        GJobs jb;
        jb.j[0] = { h, Wdkv, bdkv, ckv, DOWN_, D_, 4 };
        jb.j[1] = { h, Wdq,  bdq,  cq,  DOWN_, D_, 4 };
        jb.j[2] = jb.j[0]; jb.j[3] = jb.j[0];
        gemm_batch<<<dim3(4, 32, 2), 256, GEMM_SMEM>>>(jb);
    }
    gemm_bias<<<dim3(1, MROWS/128), 256>>>(h, Wkr, bkr, krl, MROWS, RD_, D_);

    // stage 2: kc + vc + qc + qr in one launch
    {
        GJobs jb;
        jb.j[0] = { ckv, Wuk, buk, kc, UP_,     DOWN_, 8 };
        jb.j[1] = { ckv, Wuv, buv, vc, UP_,     DOWN_, 8 };
        jb.j[2] = { cq,  Wuq, buq, qc, UP_,     DOWN_, 8 };
        jb.j[3] = { cq,  Wqr, bqr, qr, RD_*H_,  DOWN_, 4 };
        gemm_batch<<<dim3(8, 32, 4), 256, GEMM_SMEM>>>(jb);
    }

    // RoPE (negated angle)
    rope_kernel<<<MROWS, 256>>>(qr,  H_, RD_*H_);
    rope_kernel<<<MROWS, 32>>>(krl, 1,  RD_);

    // fused causal flash attention (BM=128, 8 warps)
    attn_mma<<<dim3(S_/128, H_, BS_), 256, ATT_SMEM>>>(qc, qr, kc, krl, vc, ao);

    // output projection
    {
        GJobs jb;
        jb.j[0] = { ao, Wfc, bfc, out, D_, UP_, 16 };
        jb.j[1] = jb.j[0]; jb.j[2] = jb.j[0]; jb.j[3] = jb.j[0];
        gemm_batch<<<dim3(16, 32, 1), 256, GEMM_SMEM>>>(jb);
    }
}

// round 16
// speedup vs baseline: 1.4177x; 1.2421x over previous
#include <cuda_runtime.h>
#include <cuda_bf16.h>
#include <math.h>
#include <stdint.h>

#define BS_   2
#define S_    2048
#define D_    2048
#define DOWN_ 512
#define UP_   1024
#define H_    16
#define RD_   32
#define MROWS (BS_*S_)
#define KRS   128            // padded krl row stride

#define INVSCALE (1.0f/16.970562748477139f)

__device__ float g_ckv[MROWS*DOWN_];
__device__ float g_cq [MROWS*DOWN_];
__device__ float g_krl[MROWS*KRS];      // padded: only first 32 cols used
__device__ float g_kc [MROWS*UP_];
__device__ float g_vc [MROWS*UP_];
__device__ float g_qc [MROWS*UP_];
__device__ float g_qr [MROWS*(RD_*H_)];
__device__ float g_ao [MROWS*UP_];
__device__ float g_WkrP[128*D_];        // zero-padded Wkr
__device__ float g_bkrP[128];           // zero-padded bkr

// 10000^(-j/16), j=0..15 (correctly rounded fp32)
__constant__ float c_invfreq[16] = {
    1.0f, 0.5623413251903491f, 0.31622776601683794f, 0.17782794100389228f,
    0.1f, 0.05623413251903491f, 0.031622776601683794f, 0.017782794100389228f,
    0.01f, 0.005623413251903491f, 0.0031622776601683794f, 0.0017782794100389228f,
    0.001f, 0.0005623413251903491f, 0.00031622776601683794f, 0.00017782794100389228f
};

// ---------------- bf16 helpers ----------------
__device__ __forceinline__ void mma_bf16(float* d, const uint32_t* a,
                                         const uint32_t* b) {
    asm volatile(
        "mma.sync.aligned.m16n8k16.row.col.f32.bf16.bf16.f32 "
        "{%0,%1,%2,%3},{%4,%5,%6,%7},{%8,%9},{%0,%1,%2,%3};"
        : "+f"(d[0]), "+f"(d[1]), "+f"(d[2]), "+f"(d[3])
        : "r"(a[0]), "r"(a[1]), "r"(a[2]), "r"(a[3]), "r"(b[0]), "r"(b[1]));
}
__device__ __forceinline__ uint32_t bf2_as_u32(__nv_bfloat162 v) {
    return *reinterpret_cast<uint32_t*>(&v);
}
__device__ __forceinline__ float fexp(float x) {
    x = fmaxf(x, -87.0f);
    float t = x * 1.4426950408889634f;
    float n = rintf(t);
    float f = t - n;
    float p = 0.0013333558f;
    p = fmaf(p, f, 0.009618129f);
    p = fmaf(p, f, 0.0555041087f);
    p = fmaf(p, f, 0.2402265069f);
    p = fmaf(p, f, 0.6931471806f);
    p = fmaf(p, f, 1.0f);
    return p * __int_as_float(((int)n + 127) << 23);
}

// ---- pad Wkr(32xD) + bkr(32) into 128-row zero-padded buffers ----
__global__ void pad_wkr(const float* __restrict__ Wkr, const float* __restrict__ bkr,
                        float* __restrict__ WkrP, float* __restrict__ bkrP)
{
    long n = 128L*D_;
    for (long i = blockIdx.x*(long)blockDim.x + threadIdx.x; i < n;
         i += (long)gridDim.x*blockDim.x) {
        long row = i / D_;
        WkrP[i] = (row < RD_) ? Wkr[i] : 0.f;
    }
    if (blockIdx.x == 0 && threadIdx.x < 128)
        bkrP[threadIdx.x] = (threadIdx.x < RD_) ? bkr[threadIdx.x] : 0.f;
}

// ---- batched tensor-core GEMM (3xBF16, split-at-load) ----
struct GJob { const float* A; const float* Bw; const float* bias; float* C;
              int N; int K; int nx; };
struct GJobs { GJob j[4]; };

#define PBK   20
#define PLANE (128*PBK)
__global__ void __launch_bounds__(256, 1) gemm_batch(GJobs jobs)
{
    extern __shared__ uint32_t smu[];
    const GJob job = jobs.j[blockIdx.z];
    if ((int)blockIdx.x >= job.nx) return;
    const int N = job.N, K = job.K;
    const float* __restrict__ A  = job.A;
    const float* __restrict__ Bw = job.Bw;

    const int tid  = threadIdx.x;
    const int lane = tid & 31, warp = tid >> 5;
    const int wm = warp >> 2, wn = warp & 3;
    const int lr = lane >> 2, lc = lane & 3;
    const int rowBase = blockIdx.y*128, colBase = blockIdx.x*128;
    const float* Ag = A  + (size_t)rowBase*K;
    const float* Bg = Bw + (size_t)colBase*K;

    float acc[4][4][4];
    #pragma unroll
    for (int i = 0; i < 4; i++)
        #pragma unroll
        for (int j = 0; j < 4; j++)
            #pragma unroll
            for (int c = 0; c < 4; c++) acc[i][j][c] = 0.f;

    auto load_stage = [&](int st, int k0) {
        uint32_t* base = smu + st*4*PLANE;
        #pragma unroll
        for (int i = 0; i < 4; i++) {
            int q = tid + i*256;
            int row = q >> 3, kq = (q & 7)*4;
            int col = kq >> 1;
            uint32_t* dst = base + row*PBK + col;
            float4 va = *(const float4*)(Ag + (size_t)row*K + k0 + kq);
            __nv_bfloat162 h01 = __floats2bfloat162_rn(va.x, va.y);
            __nv_bfloat162 h23 = __floats2bfloat162_rn(va.z, va.w);
            float l0 = va.x - __low2float(h01), l1 = va.y - __high2float(h01);
            float l2 = va.z - __low2float(h23), l3 = va.w - __high2float(h23);
            dst[0] = bf2_as_u32(h01); dst[1] = bf2_as_u32(h23);
            dst[PLANE+0] = bf2_as_u32(__floats2bfloat162_rn(l0, l1));
            dst[PLANE+1] = bf2_as_u32(__floats2bfloat162_rn(l2, l3));
            float4 vb = *(const float4*)(Bg + (size_t)row*K + k0 + kq);
            __nv_bfloat162 g01 = __floats2bfloat162_rn(vb.x, vb.y);
            __nv_bfloat162 g23 = __floats2bfloat162_rn(vb.z, vb.w);
            float m0 = vb.x - __low2float(g01), m1 = vb.y - __high2float(g01);
            float m2 = vb.z - __low2float(g23), m3 = vb.w - __high2float(g23);
            dst[2*PLANE+0] = bf2_as_u32(g01); dst[2*PLANE+1] = bf2_as_u32(g23);
            dst[3*PLANE+0] = bf2_as_u32(__floats2bfloat162_rn(m0, m1));
            dst[3*PLANE+1] = bf2_as_u32(__floats2bfloat162_rn(m2, m3));
        }
    };

    load_stage(0, 0);
    __syncthreads();

    const int nK = K >> 5;
    for (int t = 0; t < nK; t++) {
        const int cur = t & 1;
        if (t + 1 < nK) load_stage(cur ^ 1, (t + 1) << 5);

        const uint32_t* Ah = smu + cur*4*PLANE;
        #pragma unroll
        for (int s = 0; s < 2; s++) {
            const int colb = s*8;
            uint32_t ah[4][4], al[4][4];
            #pragma unroll
            for (int mi = 0; mi < 4; mi++) {
                const uint32_t* pa = Ah + (wm*64 + mi*16 + lr)*PBK + colb + lc;
                ah[mi][0] = pa[0];         ah[mi][2] = pa[4];
                ah[mi][1] = pa[8*PBK];     ah[mi][3] = pa[8*PBK + 4];
                const uint32_t* qa = pa + PLANE;
                al[mi][0] = qa[0];         al[mi][2] = qa[4];
                al[mi][1] = qa[8*PBK];     al[mi][3] = qa[8*PBK + 4];
            }
            #pragma unroll
            for (int ni = 0; ni < 4; ni++) {
                const uint32_t* pb = Ah + 2*PLANE + (wn*32 + ni*8 + lr)*PBK + colb + lc;
                uint32_t bh[2] = {pb[0], pb[4]};
                uint32_t bl[2] = {pb[PLANE], pb[PLANE + 4]};
                #pragma unroll
                for (int mi = 0; mi < 4; mi++) {
                    mma_bf16(acc[mi][ni], ah[mi], bh);
                    mma_bf16(acc[mi][ni], ah[mi], bl);
                    mma_bf16(acc[mi][ni], al[mi], bh);
                }
            }
        }
        __syncthreads();
    }

    float* C = job.C;
    const float* bias = job.bias;
    #pragma unroll
    for (int mi = 0; mi < 4; mi++) {
        #pragma unroll
        for (int ni = 0; ni < 4; ni++) {
            int r0 = rowBase + wm*64 + mi*16 + lr;
            int c0 = colBase + wn*32 + ni*8 + lc*2;
            float2 bv = *(const float2*)&bias[c0];
            float2 v0 = {acc[mi][ni][0] + bv.x, acc[mi][ni][1] + bv.y};
            float2 v1 = {acc[mi][ni][2] + bv.x, acc[mi][ni][3] + bv.y};
            *(float2*)&C[(size_t)r0*N + c0]       = v0;
            *(float2*)&C[(size_t)(r0 + 8)*N + c0] = v1;
        }
    }
}

// ---- RoPE in place, head_dim 32, NEGATED angle, fp32-only ----
__global__ void rope_kernel(float* __restrict__ x, int nheads, int rowStride)
{
    int row = blockIdx.x;
    int pos = row & (S_ - 1);
    int t = threadIdx.x;
    if (t >= nheads*16) return;
    int hh = t >> 4, j = t & 15;
    float* p = x + (size_t)row*rowStride + hh*32;
    float theta = (float)pos * c_invfreq[j];
    float c, sn;
    sincosf(theta, &c, &sn);
    float x1 = p[j], x2 = p[j + 16];
    p[j]      = x1*c + x2*sn;
    p[j + 16] = x2*c - x1*sn;
}

// ---- Flash attention (causal), mma bf16x3, BM=128 (8 warps) ----
#define AP 52
#define VP 36
__global__ void __launch_bounds__(256) attn_mma(
    const float* __restrict__ qc, const float* __restrict__ qrr,
    const float* __restrict__ kc, const float* __restrict__ krr,
    const float* __restrict__ vc, float* __restrict__ out)
{
    extern __shared__ uint32_t su[];
    uint32_t* Qhi = su;
    uint32_t* Qlo = Qhi + 128*AP;
    uint32_t* Khi = Qlo + 128*AP;
    uint32_t* Klo = Khi + 64*AP;
    uint32_t* Vhi = Klo + 64*AP;
    uint32_t* Vlo = Vhi + 64*VP;
    uint16_t* VhiH = (uint16_t*)Vhi;
    uint16_t* VloH = (uint16_t*)Vlo;

    const int tid = threadIdx.x;
    const int lane = tid & 31, warp = tid >> 5;
    const int lr = lane >> 2, lc = lane & 3;
    const int qb = blockIdx.x, h = blockIdx.y, b = blockIdx.z;
    const int qs = qb*128;
    const int rowOff = b*S_;

    for (int t = tid; t < 128*24; t += 256) {
        int r = t / 24, w = t - (t/24)*24;
        int grow = rowOff + qs + r;
        float4 v = (w < 16)
            ? *(const float4*)(qc  + (size_t)grow*UP_      + h*64 + 4*w)
            : *(const float4*)(qrr + (size_t)grow*(RD_*H_) + h*32 + 4*(w-16));
        __nv_bfloat162 h01 = __floats2bfloat162_rn(v.x, v.y);
        __nv_bfloat162 h23 = __floats2bfloat162_rn(v.z, v.w);
        float e0 = v.x - __low2float(h01), e1 = v.y - __high2float(h01);
        float e2 = v.z - __low2float(h23), e3 = v.w - __high2float(h23);
        Qhi[r*AP + 2*w]   = bf2_as_u32(h01);
        Qhi[r*AP + 2*w+1] = bf2_as_u32(h23);
        Qlo[r*AP + 2*w]   = bf2_as_u32(__floats2bfloat162_rn(e0, e1));
        Qlo[r*AP + 2*w+1] = bf2_as_u32(__floats2bfloat162_rn(e2, e3));
    }

    float m0 = -1e30f, m1 = -1e30f, l0s = 0.f, l1s = 0.f;
    float o[8][4];
    #pragma unroll
    for (int j = 0; j < 8; j++)
        #pragma unroll
        for (int c = 0; c < 4; c++) o[j][c] = 0.f;

    for (int kb = 0; kb <= qs + 64; kb += 64) {
        __syncthreads();
        for (int t = tid; t < 64*24; t += 256) {
            int r = t / 24, w = t - (t/24)*24;
            int grow = rowOff + kb + r;
            float4 v = (w < 16)
                ? *(const float4*)(kc  + (size_t)grow*UP_ + h*64 + 4*w)
                : *(const float4*)(krr + (size_t)grow*KRS + 4*(w-16));
            __nv_bfloat162 h01 = __floats2bfloat162_rn(v.x, v.y);
            __nv_bfloat162 h23 = __floats2bfloat162_rn(v.z, v.w);
            float e0 = v.x - __low2float(h01), e1 = v.y - __high2float(h01);
            float e2 = v.z - __low2float(h23), e3 = v.w - __high2float(h23);
            Khi[r*AP + 2*w]   = bf2_as_u32(h01);
            Khi[r*AP + 2*w+1] = bf2_as_u32(h23);
            Klo[r*AP + 2*w]   = bf2_as_u32(__floats2bfloat162_rn(e0, e1));
            Klo[r*AP + 2*w+1] = bf2_as_u32(__floats2bfloat162_rn(e2, e3));
        }
        for (int t = tid; t < 64*16; t += 256) {
            int r = t / 16, dq = t - (t/16)*16;
            int grow = rowOff + kb + r;
            float4 v = *(const float4*)(vc + (size_t)grow*UP_ + h*64 + 4*dq);
            float vv[4] = {v.x, v.y, v.z, v.w};
            #pragma unroll
            for (int e = 0; e < 4; e++) {
                int d = 4*dq + e;
                __nv_bfloat16 hb = __float2bfloat16_rn(vv[e]);
                float rem = vv[e] - __bfloat162float(hb);
                __nv_bfloat16 lb = __float2bfloat16_rn(rem);
                VhiH[d*(2*VP) + r] = *(uint16_t*)&hb;
                VloH[d*(2*VP) + r] = *(uint16_t*)&lb;
            }
        }
        __syncthreads();

        float s[8][4];
        #pragma unroll
        for (int j = 0; j < 8; j++)
            #pragma unroll
            for (int c = 0; c < 4; c++) s[j][c] = 0.f;

        const uint32_t* qh = Qhi + (warp*16 + lr)*AP + lc;
        const uint32_t* ql = Qlo + (warp*16 + lr)*AP + lc;
        #pragma unroll
        for (int t = 0; t < 6; t++) {
            uint32_t ah[4], al[4];
            const uint32_t* pq = qh + t*8;
            ah[0]=pq[0]; ah[1]=pq[8*AP]; ah[2]=pq[4]; ah[3]=pq[8*AP+4];
            const uint32_t* pl = ql + t*8;
            al[0]=pl[0]; al[1]=pl[8*AP]; al[2]=pl[4]; al[3]=pl[8*AP+4];
            #pragma unroll
            for (int j = 0; j < 8; j++) {
                const uint32_t* pk = Khi + (8*j + lr)*AP + t*8 + lc;
                uint32_t bh[2] = {pk[0], pk[4]};
                const uint32_t* kl = Klo + (8*j + lr)*AP + t*8 + lc;
                uint32_t bl[2] = {kl[0], kl[4]};
                mma_bf16(s[j], ah, bh);
                mma_bf16(s[j], ah, bl);
                mma_bf16(s[j], al, bh);
            }
        }

        const int row0 = qs + warp*16 + lr, row1 = row0 + 8;
        #pragma unroll
        for (int j = 0; j < 8; j++) {
            int c0 = kb + 8*j + 2*lc, c1 = c0 + 1;
            s[j][0] = (c0 > row0) ? -1e30f : s[j][0]*INVSCALE;
            s[j][1] = (c1 > row0) ? -1e30f : s[j][1]*INVSCALE;
            s[j][2] = (c0 > row1) ? -1e30f : s[j][2]*INVSCALE;
            s[j][3] = (c1 > row1) ? -1e30f : s[j][3]*INVSCALE;
        }

        float rm0 = -1e30f, rm1 = -1e30f;
        #pragma unroll
        for (int j = 0; j < 8; j++) {
            rm0 = fmaxf(rm0, fmaxf(s[j][0], s[j][1]));
            rm1 = fmaxf(rm1, fmaxf(s[j][2], s[j][3]));
        }
        rm0 = fmaxf(rm0, __shfl_xor_sync(0xffffffffu, rm0, 1));
        rm0 = fmaxf(rm0, __shfl_xor_sync(0xffffffffu, rm0, 2));
        rm1 = fmaxf(rm1, __shfl_xor_sync(0xffffffffu, rm1, 1));
        rm1 = fmaxf(rm1, __shfl_xor_sync(0xffffffffu, rm1, 2));
        float mn0 = fmaxf(m0, rm0), mn1 = fmaxf(m1, rm1);
        float cr0 = fexp(m0 - mn0), cr1 = fexp(m1 - mn1);
        l0s *= cr0; l1s *= cr1;
        #pragma unroll
        for (int j = 0; j < 8; j++) {
            o[j][0] *= cr0; o[j][1] *= cr0;
            o[j][2] *= cr1; o[j][3] *= cr1;
        }
        uint32_t phi[8][2], plo[8][2];
        float rs0 = 0.f, rs1 = 0.f;
        #pragma unroll
        for (int j = 0; j < 8; j++) {
            float p0 = fexp(s[j][0] - mn0), p1 = fexp(s[j][1] - mn0);
            float p2 = fexp(s[j][2] - mn1), p3 = fexp(s[j][3] - mn1);
            rs0 += p0 + p1; rs1 += p2 + p3;
            __nv_bfloat162 h01 = __floats2bfloat162_rn(p0, p1);
            __nv_bfloat162 h23 = __floats2bfloat162_rn(p2, p3);
            phi[j][0] = bf2_as_u32(h01);
            phi[j][1] = bf2_as_u32(h23);
            plo[j][0] = bf2_as_u32(__floats2bfloat162_rn(
                p0 - __low2float(h01), p1 - __high2float(h01)));
            plo[j][1] = bf2_as_u32(__floats2bfloat162_rn(
                p2 - __low2float(h23), p3 - __high2float(h23)));
        }
        rs0 += __shfl_xor_sync(0xffffffffu, rs0, 1);
        rs0 += __shfl_xor_sync(0xffffffffu, rs0, 2);
        rs1 += __shfl_xor_sync(0xffffffffu, rs1, 1);
        rs1 += __shfl_xor_sync(0xffffffffu, rs1, 2);
        l0s += rs0; l1s += rs1; m0 = mn0; m1 = mn1;

        #pragma unroll
        for (int t = 0; t < 4; t++) {
            uint32_t ah[4] = {phi[2*t][0], phi[2*t][1], phi[2*t+1][0], phi[2*t+1][1]};
            uint32_t al[4] = {plo[2*t][0], plo[2*t][1], plo[2*t+1][0], plo[2*t+1][1]};
            #pragma unroll
            for (int j = 0; j < 8; j++) {
                const uint32_t* pv = Vhi + (8*j + lr)*VP + t*8 + lc;
                uint32_t bh[2] = {pv[0], pv[4]};
                const uint32_t* pw = Vlo + (8*j + lr)*VP + t*8 + lc;
                uint32_t bl[2] = {pw[0], pw[4]};
                mma_bf16(o[j], ah, bh);
                mma_bf16(o[j], ah, bl);
                mma_bf16(o[j], al, bh);
            }
        }
    }

    float inv0 = 1.f / l0s, inv1 = 1.f / l1s;
    int grow0 = rowOff + qs + warp*16 + lr;
    #pragma unroll
    for (int j = 0; j < 8; j++) {
        int col = h*64 + 8*j + 2*lc;
        float2 v0 = {o[j][0]*inv0, o[j][1]*inv0};
        float2 v1 = {o[j][2]*inv1, o[j][3]*inv1};
        *(float2*)&out[(size_t)grow0*UP_ + col]     = v0;
        *(float2*)&out[(size_t)(grow0+8)*UP_ + col] = v1;
    }
}

extern "C" void kernel_launch(void* const* d_in, const int* in_sizes, int n_in,
                              void* d_out, int out_size)
{
    const float* h    = (const float*)d_in[0];
    const float* Wdkv = (const float*)d_in[2];  const float* bdkv = (const float*)d_in[3];
    const float* Wuk  = (const float*)d_in[4];  const float* buk  = (const float*)d_in[5];
    const float* Wuv  = (const float*)d_in[6];  const float* buv  = (const float*)d_in[7];
    const float* Wdq  = (const float*)d_in[8];  const float* bdq  = (const float*)d_in[9];
    const float* Wuq  = (const float*)d_in[10]; const float* buq  = (const float*)d_in[11];
    const float* Wqr  = (const float*)d_in[12]; const float* bqr  = (const float*)d_in[13];
    const float* Wkr  = (const float*)d_in[14]; const float* bkr  = (const float*)d_in[15];
    const float* Wfc  = (const float*)d_in[16]; const float* bfc  = (const float*)d_in[17];
    float* out = (float*)d_out;

    float *ckv, *cq, *krl, *kc, *vc, *qc, *qr, *ao, *WkrP, *bkrP;
    cudaGetSymbolAddress((void**)&ckv, g_ckv);
    cudaGetSymbolAddress((void**)&cq,  g_cq);
    cudaGetSymbolAddress((void**)&krl, g_krl);
    cudaGetSymbolAddress((void**)&kc,  g_kc);
    cudaGetSymbolAddress((void**)&vc,  g_vc);
    cudaGetSymbolAddress((void**)&qc,  g_qc);
    cudaGetSymbolAddress((void**)&qr,  g_qr);
    cudaGetSymbolAddress((void**)&ao,  g_ao);
    cudaGetSymbolAddress((void**)&WkrP, g_WkrP);
    cudaGetSymbolAddress((void**)&bkrP, g_bkrP);

    const int ATT_SMEM  = (2*128*AP + 2*64*AP + 2*64*VP)*(int)sizeof(uint32_t);
    const int GEMM_SMEM = 2*4*PLANE*(int)sizeof(uint32_t);
    cudaFuncSetAttribute(attn_mma,
                         cudaFuncAttributeMaxDynamicSharedMemorySize, ATT_SMEM);
    cudaFuncSetAttribute(gemm_batch,
                         cudaFuncAttributeMaxDynamicSharedMemorySize, GEMM_SMEM);

    // pad Wkr/bkr to 128 rows so krl rides the batched tensor-core GEMM
    pad_wkr<<<256, 256>>>(Wkr, bkr, WkrP, bkrP);

    // stage 1: ckv + cq + krl in one launch
    {
        GJobs jb;
        jb.j[0] = { h, Wdkv, bdkv, ckv, DOWN_, D_, 4 };
        jb.j[1] = { h, Wdq,  bdq,  cq,  DOWN_, D_, 4 };
        jb.j[2] = { h, WkrP, bkrP, krl, KRS,   D_, 1 };
        jb.j[3] = jb.j[2];
        gemm_batch<<<dim3(4, 32, 3), 256, GEMM_SMEM>>>(jb);
    }

    // stage 2: kc + vc + qc + qr in one launch
    {
        GJobs jb;
        jb.j[0] = { ckv, Wuk, buk, kc, UP_,     DOWN_, 8 };
        jb.j[1] = { ckv, Wuv, buv, vc, UP_,     DOWN_, 8 };
        jb.j[2] = { cq,  Wuq, buq, qc, UP_,     DOWN_, 8 };
        jb.j[3] = { cq,  Wqr, bqr, qr, RD_*H_,  DOWN_, 4 };
        gemm_batch<<<dim3(8, 32, 4), 256, GEMM_SMEM>>>(jb);
    }

    // RoPE (negated angle, fp32-only)
    rope_kernel<<<MROWS, 256>>>(qr,  H_, RD_*H_);
    rope_kernel<<<MROWS, 32>>>(krl, 1,  KRS);

    // fused causal flash attention (BM=128, 8 warps)
    attn_mma<<<dim3(S_/128, H_, BS_), 256, ATT_SMEM>>>(qc, qr, kc, krl, vc, ao);

    // output projection
    {
        GJobs jb;
        jb.j[0] = { ao, Wfc, bfc, out, D_, UP_, 16 };
        jb.j[1] = jb.j[0]; jb.j[2] = jb.j[0]; jb.j[3] = jb.j[0];
        gemm_batch<<<dim3(16, 32, 1), 256, GEMM_SMEM>>>(jb);
    }
}

// round 17
// speedup vs baseline: 1.4667x; 1.0346x over previous
#include <cuda_runtime.h>
#include <cuda_bf16.h>
#include <math.h>
#include <stdint.h>

#define BS_   2
#define S_    2048
#define D_    2048
#define DOWN_ 512
#define UP_   1024
#define H_    16
#define RD_   32
#define MROWS (BS_*S_)
#define KRS   128

#define INVSCALE (1.0f/16.970562748477139f)

__device__ float g_ckv[MROWS*DOWN_];
__device__ float g_cq [MROWS*DOWN_];
__device__ float g_krl[MROWS*KRS];
__device__ float g_kc [MROWS*UP_];
__device__ float g_vc [MROWS*UP_];
__device__ float g_qc [MROWS*UP_];
__device__ float g_qr [MROWS*(RD_*H_)];
__device__ float g_ao [MROWS*UP_];
__device__ float g_WkrP[128*D_];
__device__ float g_bkrP[128];

__constant__ float c_invfreq[16] = {
    1.0f, 0.5623413251903491f, 0.31622776601683794f, 0.17782794100389228f,
    0.1f, 0.05623413251903491f, 0.031622776601683794f, 0.017782794100389228f,
    0.01f, 0.005623413251903491f, 0.0031622776601683794f, 0.0017782794100389228f,
    0.001f, 0.0005623413251903491f, 0.00031622776601683794f, 0.00017782794100389228f
};

// ---------------- helpers ----------------
__device__ __forceinline__ void mma_bf16(float* d, const uint32_t* a,
                                         const uint32_t* b) {
    asm volatile(
        "mma.sync.aligned.m16n8k16.row.col.f32.bf16.bf16.f32 "
        "{%0,%1,%2,%3},{%4,%5,%6,%7},{%8,%9},{%0,%1,%2,%3};"
        : "+f"(d[0]), "+f"(d[1]), "+f"(d[2]), "+f"(d[3])
        : "r"(a[0]), "r"(a[1]), "r"(a[2]), "r"(a[3]), "r"(b[0]), "r"(b[1]));
}
__device__ __forceinline__ void ldsm_x4(uint32_t* r, uint32_t addr) {
    asm volatile("ldmatrix.sync.aligned.m8n8.x4.shared.b16 {%0,%1,%2,%3}, [%4];"
        : "=r"(r[0]), "=r"(r[1]), "=r"(r[2]), "=r"(r[3]) : "r"(addr));
}
__device__ __forceinline__ uint32_t bf2_as_u32(__nv_bfloat162 v) {
    return *reinterpret_cast<uint32_t*>(&v);
}
__device__ __forceinline__ float fexp(float x) {
    x = fmaxf(x, -87.0f);
    float t = x * 1.4426950408889634f;
    float n = rintf(t);
    float f = t - n;
    float p = 0.0013333558f;
    p = fmaf(p, f, 0.009618129f);
    p = fmaf(p, f, 0.0555041087f);
    p = fmaf(p, f, 0.2402265069f);
    p = fmaf(p, f, 0.6931471806f);
    p = fmaf(p, f, 1.0f);
    return p * __int_as_float(((int)n + 127) << 23);
}

// ---- pad Wkr/bkr ----
__global__ void pad_wkr(const float* __restrict__ Wkr, const float* __restrict__ bkr,
                        float* __restrict__ WkrP, float* __restrict__ bkrP)
{
    long n = 128L*D_;
    for (long i = blockIdx.x*(long)blockDim.x + threadIdx.x; i < n;
         i += (long)gridDim.x*blockDim.x) {
        long row = i / D_;
        WkrP[i] = (row < RD_) ? Wkr[i] : 0.f;
    }
    if (blockIdx.x == 0 && threadIdx.x < 128)
        bkrP[threadIdx.x] = (threadIdx.x < RD_) ? bkr[threadIdx.x] : 0.f;
}

// ---- batched tensor-core GEMM (3xBF16, ldmatrix fragments) ----
struct GJob { const float* A; const float* Bw; const float* bias; float* C;
              int N; int K; int nx; };
struct GJobs { GJob j[4]; };

#define PBK   20
#define PLANE (128*PBK)
__global__ void __launch_bounds__(256, 1) gemm_batch(GJobs jobs)
{
    extern __shared__ uint32_t smu[];
    const GJob job = jobs.j[blockIdx.z];
    if ((int)blockIdx.x >= job.nx) return;
    const int N = job.N, K = job.K;
    const float* __restrict__ A  = job.A;
    const float* __restrict__ Bw = job.Bw;

    const int tid  = threadIdx.x;
    const int lane = tid & 31, warp = tid >> 5;
    const int wm = warp >> 2, wn = warp & 3;
    const int lr = lane >> 2, lc = lane & 3;
    const int rowBase = blockIdx.y*128, colBase = blockIdx.x*128;
    const float* Ag = A  + (size_t)rowBase*K;
    const float* Bg = Bw + (size_t)colBase*K;

    // ldmatrix per-lane row/chunk decomposition
    const int arow   = ((lane >> 3) & 1)*8 + (lane & 7);  // A / x4 tiles
    const int achunk = (lane >> 4)*4;
    const int brow   = ((lane >> 4) & 1)*8 + (lane & 7);  // B pair / x4 tiles
    const int bchunk = ((lane >> 3) & 1)*4;
    const uint32_t sbase = (uint32_t)__cvta_generic_to_shared(smu);

    float acc[4][4][4];
    #pragma unroll
    for (int i = 0; i < 4; i++)
        #pragma unroll
        for (int j = 0; j < 4; j++)
            #pragma unroll
            for (int c = 0; c < 4; c++) acc[i][j][c] = 0.f;

    auto load_stage = [&](int st, int k0) {
        uint32_t* base = smu + st*4*PLANE;
        #pragma unroll
        for (int i = 0; i < 4; i++) {
            int q = tid + i*256;
            int row = q >> 3, kq = (q & 7)*4;
            int col = kq >> 1;
            uint32_t* dst = base + row*PBK + col;
            float4 va = *(const float4*)(Ag + (size_t)row*K + k0 + kq);
            __nv_bfloat162 h01 = __floats2bfloat162_rn(va.x, va.y);
            __nv_bfloat162 h23 = __floats2bfloat162_rn(va.z, va.w);
            float l0 = va.x - __low2float(h01), l1 = va.y - __high2float(h01);
            float l2 = va.z - __low2float(h23), l3 = va.w - __high2float(h23);
            dst[0] = bf2_as_u32(h01); dst[1] = bf2_as_u32(h23);
            dst[PLANE+0] = bf2_as_u32(__floats2bfloat162_rn(l0, l1));
            dst[PLANE+1] = bf2_as_u32(__floats2bfloat162_rn(l2, l3));
            float4 vb = *(const float4*)(Bg + (size_t)row*K + k0 + kq);
            __nv_bfloat162 g01 = __floats2bfloat162_rn(vb.x, vb.y);
            __nv_bfloat162 g23 = __floats2bfloat162_rn(vb.z, vb.w);
            float m0 = vb.x - __low2float(g01), m1 = vb.y - __high2float(g01);
            float m2 = vb.z - __low2float(g23), m3 = vb.w - __high2float(g23);
            dst[2*PLANE+0] = bf2_as_u32(g01); dst[2*PLANE+1] = bf2_as_u32(g23);
            dst[3*PLANE+0] = bf2_as_u32(__floats2bfloat162_rn(m0, m1));
            dst[3*PLANE+1] = bf2_as_u32(__floats2bfloat162_rn(m2, m3));
        }
    };

    load_stage(0, 0);
    __syncthreads();

    const int nK = K >> 5;
    for (int t = 0; t < nK; t++) {
        const int cur = t & 1;
        if (t + 1 < nK) load_stage(cur ^ 1, (t + 1) << 5);

        const uint32_t abase = sbase + (cur*4*PLANE)*4;
        #pragma unroll
        for (int s = 0; s < 2; s++) {
            const int colb = s*8;
            uint32_t ah[4][4], al[4][4];
            #pragma unroll
            for (int mi = 0; mi < 4; mi++) {
                uint32_t aaddr = abase +
                    4*((wm*64 + mi*16 + arow)*PBK + colb + achunk);
                ldsm_x4(ah[mi], aaddr);
                ldsm_x4(al[mi], aaddr + PLANE*4);
            }
            uint32_t bh[2][4], bl[2][4];
            #pragma unroll
            for (int p = 0; p < 2; p++) {
                uint32_t baddr = abase + 2*PLANE*4 +
                    4*((wn*32 + 16*p + brow)*PBK + colb + bchunk);
                ldsm_x4(bh[p], baddr);
                ldsm_x4(bl[p], baddr + PLANE*4);
            }
            #pragma unroll
            for (int p = 0; p < 2; p++)
                #pragma unroll
                for (int hf = 0; hf < 2; hf++) {
                    const int ni = 2*p + hf;
                    #pragma unroll
                    for (int mi = 0; mi < 4; mi++) {
                        mma_bf16(acc[mi][ni], ah[mi], &bh[p][2*hf]);
                        mma_bf16(acc[mi][ni], ah[mi], &bl[p][2*hf]);
                        mma_bf16(acc[mi][ni], al[mi], &bh[p][2*hf]);
                    }
                }
        }
        __syncthreads();
    }

    float* C = job.C;
    const float* bias = job.bias;
    #pragma unroll
    for (int mi = 0; mi < 4; mi++) {
        #pragma unroll
        for (int ni = 0; ni < 4; ni++) {
            int r0 = rowBase + wm*64 + mi*16 + lr;
            int c0 = colBase + wn*32 + ni*8 + lc*2;
            float2 bv = *(const float2*)&bias[c0];
            float2 v0 = {acc[mi][ni][0] + bv.x, acc[mi][ni][1] + bv.y};
            float2 v1 = {acc[mi][ni][2] + bv.x, acc[mi][ni][3] + bv.y};
            *(float2*)&C[(size_t)r0*N + c0]       = v0;
            *(float2*)&C[(size_t)(r0 + 8)*N + c0] = v1;
        }
    }
}

// ---- RoPE in place, NEGATED angle ----
__global__ void rope_kernel(float* __restrict__ x, int nheads, int rowStride)
{
    int row = blockIdx.x;
    int pos = row & (S_ - 1);
    int t = threadIdx.x;
    if (t >= nheads*16) return;
    int hh = t >> 4, j = t & 15;
    float* p = x + (size_t)row*rowStride + hh*32;
    float theta = (float)pos * c_invfreq[j];
    float c, sn;
    sincosf(theta, &c, &sn);
    float x1 = p[j], x2 = p[j + 16];
    p[j]      = x1*c + x2*sn;
    p[j + 16] = x2*c - x1*sn;
}

// ---- Flash attention (causal), mma bf16x3 + ldmatrix, BM=128 ----
#define AP 52
#define VP 36
__global__ void __launch_bounds__(256) attn_mma(
    const float* __restrict__ qc, const float* __restrict__ qrr,
    const float* __restrict__ kc, const float* __restrict__ krr,
    const float* __restrict__ vc, float* __restrict__ out)
{
    extern __shared__ uint32_t su[];
    uint32_t* Qhi = su;
    uint32_t* Qlo = Qhi + 128*AP;
    uint32_t* Khi = Qlo + 128*AP;
    uint32_t* Klo = Khi + 64*AP;
    uint32_t* Vhi = Klo + 64*AP;
    uint32_t* Vlo = Vhi + 64*VP;
    uint16_t* VhiH = (uint16_t*)Vhi;
    uint16_t* VloH = (uint16_t*)Vlo;

    const int tid = threadIdx.x;
    const int lane = tid & 31, warp = tid >> 5;
    const int lr = lane >> 2, lc = lane & 3;
    const int qb = blockIdx.x, h = blockIdx.y, b = blockIdx.z;
    const int qs = qb*128;
    const int rowOff = b*S_;

    const int arow   = ((lane >> 3) & 1)*8 + (lane & 7);
    const int achunk = (lane >> 4)*4;
    const int brow   = ((lane >> 4) & 1)*8 + (lane & 7);
    const int bchunk = ((lane >> 3) & 1)*4;
    const uint32_t sbase = (uint32_t)__cvta_generic_to_shared(su);
    const uint32_t OFF_QLO = 128*AP*4;
    const uint32_t OFF_KHI = 2*128*AP*4;
    const uint32_t OFF_KLO = OFF_KHI + 64*AP*4;
    const uint32_t OFF_VHI = OFF_KLO + 64*AP*4;

    for (int t = tid; t < 128*24; t += 256) {
        int r = t / 24, w = t - (t/24)*24;
        int grow = rowOff + qs + r;
        float4 v = (w < 16)
            ? *(const float4*)(qc  + (size_t)grow*UP_      + h*64 + 4*w)
            : *(const float4*)(qrr + (size_t)grow*(RD_*H_) + h*32 + 4*(w-16));
        __nv_bfloat162 h01 = __floats2bfloat162_rn(v.x, v.y);
        __nv_bfloat162 h23 = __floats2bfloat162_rn(v.z, v.w);
        float e0 = v.x - __low2float(h01), e1 = v.y - __high2float(h01);
        float e2 = v.z - __low2float(h23), e3 = v.w - __high2float(h23);
        Qhi[r*AP + 2*w]   = bf2_as_u32(h01);
        Qhi[r*AP + 2*w+1] = bf2_as_u32(h23);
        Qlo[r*AP + 2*w]   = bf2_as_u32(__floats2bfloat162_rn(e0, e1));
        Qlo[r*AP + 2*w+1] = bf2_as_u32(__floats2bfloat162_rn(e2, e3));
    }

    float m0 = -1e30f, m1 = -1e30f, l0s = 0.f, l1s = 0.f;
    float o[8][4];
    #pragma unroll
    for (int j = 0; j < 8; j++)
        #pragma unroll
        for (int c = 0; c < 4; c++) o[j][c] = 0.f;

    for (int kb = 0; kb <= qs + 64; kb += 64) {
        __syncthreads();
        for (int t = tid; t < 64*24; t += 256) {
            int r = t / 24, w = t - (t/24)*24;
            int grow = rowOff + kb + r;
            float4 v = (w < 16)
                ? *(const float4*)(kc  + (size_t)grow*UP_ + h*64 + 4*w)
                : *(const float4*)(krr + (size_t)grow*KRS + 4*(w-16));
            __nv_bfloat162 h01 = __floats2bfloat162_rn(v.x, v.y);
            __nv_bfloat162 h23 = __floats2bfloat162_rn(v.z, v.w);
            float e0 = v.x - __low2float(h01), e1 = v.y - __high2float(h01);
            float e2 = v.z - __low2float(h23), e3 = v.w - __high2float(h23);
            Khi[r*AP + 2*w]   = bf2_as_u32(h01);
            Khi[r*AP + 2*w+1] = bf2_as_u32(h23);
            Klo[r*AP + 2*w]   = bf2_as_u32(__floats2bfloat162_rn(e0, e1));
            Klo[r*AP + 2*w+1] = bf2_as_u32(__floats2bfloat162_rn(e2, e3));
        }
        for (int t = tid; t < 64*16; t += 256) {
            int r = t / 16, dq = t - (t/16)*16;
            int grow = rowOff + kb + r;
            float4 v = *(const float4*)(vc + (size_t)grow*UP_ + h*64 + 4*dq);
            float vv[4] = {v.x, v.y, v.z, v.w};
            #pragma unroll
            for (int e = 0; e < 4; e++) {
                int d = 4*dq + e;
                __nv_bfloat16 hb = __float2bfloat16_rn(vv[e]);
                float rem = vv[e] - __bfloat162float(hb);
                __nv_bfloat16 lb = __float2bfloat16_rn(rem);
                VhiH[d*(2*VP) + r] = *(uint16_t*)&hb;
                VloH[d*(2*VP) + r] = *(uint16_t*)&lb;
            }
        }
        __syncthreads();

        float s[8][4];
        #pragma unroll
        for (int j = 0; j < 8; j++)
            #pragma unroll
            for (int c = 0; c < 4; c++) s[j][c] = 0.f;

        #pragma unroll
        for (int t = 0; t < 6; t++) {
            uint32_t ah[4], al[4];
            uint32_t qaddr = sbase + 4*((warp*16 + arow)*AP + t*8 + achunk);
            ldsm_x4(ah, qaddr);
            ldsm_x4(al, qaddr + OFF_QLO);
            #pragma unroll
            for (int jp = 0; jp < 4; jp++) {
                uint32_t bh[4], bl[4];
                uint32_t kaddr = sbase + OFF_KHI +
                    4*((16*jp + brow)*AP + t*8 + bchunk);
                ldsm_x4(bh, kaddr);
                ldsm_x4(bl, kaddr + 64*AP*4);
                mma_bf16(s[2*jp],   ah, &bh[0]);
                mma_bf16(s[2*jp],   ah, &bl[0]);
                mma_bf16(s[2*jp],   al, &bh[0]);
                mma_bf16(s[2*jp+1], ah, &bh[2]);
                mma_bf16(s[2*jp+1], ah, &bl[2]);
                mma_bf16(s[2*jp+1], al, &bh[2]);
            }
        }

        const int row0 = qs + warp*16 + lr, row1 = row0 + 8;
        #pragma unroll
        for (int j = 0; j < 8; j++) {
            int c0 = kb + 8*j + 2*lc, c1 = c0 + 1;
            s[j][0] = (c0 > row0) ? -1e30f : s[j][0]*INVSCALE;
            s[j][1] = (c1 > row0) ? -1e30f : s[j][1]*INVSCALE;
            s[j][2] = (c0 > row1) ? -1e30f : s[j][2]*INVSCALE;
            s[j][3] = (c1 > row1) ? -1e30f : s[j][3]*INVSCALE;
        }

        float rm0 = -1e30f, rm1 = -1e30f;
        #pragma unroll
        for (int j = 0; j < 8; j++) {
            rm0 = fmaxf(rm0, fmaxf(s[j][0], s[j][1]));
            rm1 = fmaxf(rm1, fmaxf(s[j][2], s[j][3]));
        }
        rm0 = fmaxf(rm0, __shfl_xor_sync(0xffffffffu, rm0, 1));
        rm0 = fmaxf(rm0, __shfl_xor_sync(0xffffffffu, rm0, 2));
        rm1 = fmaxf(rm1, __shfl_xor_sync(0xffffffffu, rm1, 1));
        rm1 = fmaxf(rm1, __shfl_xor_sync(0xffffffffu, rm1, 2));
        float mn0 = fmaxf(m0, rm0), mn1 = fmaxf(m1, rm1);
        float cr0 = fexp(m0 - mn0), cr1 = fexp(m1 - mn1);
        l0s *= cr0; l1s *= cr1;
        #pragma unroll
        for (int j = 0; j < 8; j++) {
            o[j][0] *= cr0; o[j][1] *= cr0;
            o[j][2] *= cr1; o[j][3] *= cr1;
        }
        uint32_t phi[8][2], plo[8][2];
        float rs0 = 0.f, rs1 = 0.f;
        #pragma unroll
        for (int j = 0; j < 8; j++) {
            float p0 = fexp(s[j][0] - mn0), p1 = fexp(s[j][1] - mn0);
            float p2 = fexp(s[j][2] - mn1), p3 = fexp(s[j][3] - mn1);
            rs0 += p0 + p1; rs1 += p2 + p3;
            __nv_bfloat162 h01 = __floats2bfloat162_rn(p0, p1);
            __nv_bfloat162 h23 = __floats2bfloat162_rn(p2, p3);
            phi[j][0] = bf2_as_u32(h01);
            phi[j][1] = bf2_as_u32(h23);
            plo[j][0] = bf2_as_u32(__floats2bfloat162_rn(
                p0 - __low2float(h01), p1 - __high2float(h01)));
            plo[j][1] = bf2_as_u32(__floats2bfloat162_rn(
                p2 - __low2float(h23), p3 - __high2float(h23)));
        }
        rs0 += __shfl_xor_sync(0xffffffffu, rs0, 1);
        rs0 += __shfl_xor_sync(0xffffffffu, rs0, 2);
        rs1 += __shfl_xor_sync(0xffffffffu, rs1, 1);
        rs1 += __shfl_xor_sync(0xffffffffu, rs1, 2);
        l0s += rs0; l1s += rs1; m0 = mn0; m1 = mn1;

        #pragma unroll
        for (int t = 0; t < 4; t++) {
            uint32_t ah[4] = {phi[2*t][0], phi[2*t][1], phi[2*t+1][0], phi[2*t+1][1]};
            uint32_t al[4] = {plo[2*t][0], plo[2*t][1], plo[2*t+1][0], plo[2*t+1][1]};
            #pragma unroll
            for (int jp = 0; jp < 4; jp++) {
                uint32_t bh[4], bl[4];
                uint32_t vaddr = sbase + OFF_VHI +
                    4*((16*jp + brow)*VP + t*8 + bchunk);
                ldsm_x4(bh, vaddr);
                ldsm_x4(bl, vaddr + 64*VP*4);
                mma_bf16(o[2*jp],   ah, &bh[0]);
                mma_bf16(o[2*jp],   ah, &bl[0]);
                mma_bf16(o[2*jp],   al, &bh[0]);
                mma_bf16(o[2*jp+1], ah, &bh[2]);
                mma_bf16(o[2*jp+1], ah, &bl[2]);
                mma_bf16(o[2*jp+1], al, &bh[2]);
            }
        }
    }

    float inv0 = 1.f / l0s, inv1 = 1.f / l1s;
    int grow0 = rowOff + qs + warp*16 + lr;
    #pragma unroll
    for (int j = 0; j < 8; j++) {
        int col = h*64 + 8*j + 2*lc;
        float2 v0 = {o[j][0]*inv0, o[j][1]*inv0};
        float2 v1 = {o[j][2]*inv1, o[j][3]*inv1};
        *(float2*)&out[(size_t)grow0*UP_ + col]     = v0;
        *(float2*)&out[(size_t)(grow0+8)*UP_ + col] = v1;
    }
}

extern "C" void kernel_launch(void* const* d_in, const int* in_sizes, int n_in,
                              void* d_out, int out_size)
{
    const float* h    = (const float*)d_in[0];
    const float* Wdkv = (const float*)d_in[2];  const float* bdkv = (const float*)d_in[3];
    const float* Wuk  = (const float*)d_in[4];  const float* buk  = (const float*)d_in[5];
    const float* Wuv  = (const float*)d_in[6];  const float* buv  = (const float*)d_in[7];
    const float* Wdq  = (const float*)d_in[8];  const float* bdq  = (const float*)d_in[9];
    const float* Wuq  = (const float*)d_in[10]; const float* buq  = (const float*)d_in[11];
    const float* Wqr  = (const float*)d_in[12]; const float* bqr  = (const float*)d_in[13];
    const float* Wkr  = (const float*)d_in[14]; const float* bkr  = (const float*)d_in[15];
    const float* Wfc  = (const float*)d_in[16]; const float* bfc  = (const float*)d_in[17];
    float* out = (float*)d_out;

    float *ckv, *cq, *krl, *kc, *vc, *qc, *qr, *ao, *WkrP, *bkrP;
    cudaGetSymbolAddress((void**)&ckv, g_ckv);
    cudaGetSymbolAddress((void**)&cq,  g_cq);
    cudaGetSymbolAddress((void**)&krl, g_krl);
    cudaGetSymbolAddress((void**)&kc,  g_kc);
    cudaGetSymbolAddress((void**)&vc,  g_vc);
    cudaGetSymbolAddress((void**)&qc,  g_qc);
    cudaGetSymbolAddress((void**)&qr,  g_qr);
    cudaGetSymbolAddress((void**)&ao,  g_ao);
    cudaGetSymbolAddress((void**)&WkrP, g_WkrP);
    cudaGetSymbolAddress((void**)&bkrP, g_bkrP);

    const int ATT_SMEM  = (2*128*AP + 2*64*AP + 2*64*VP)*(int)sizeof(uint32_t);
    const int GEMM_SMEM = 2*4*PLANE*(int)sizeof(uint32_t);
    cudaFuncSetAttribute(attn_mma,
                         cudaFuncAttributeMaxDynamicSharedMemorySize, ATT_SMEM);
    cudaFuncSetAttribute(gemm_batch,
                         cudaFuncAttributeMaxDynamicSharedMemorySize, GEMM_SMEM);

    pad_wkr<<<256, 256>>>(Wkr, bkr, WkrP, bkrP);

    // stage 1: ckv + cq + krl
    {
        GJobs jb;
        jb.j[0] = { h, Wdkv, bdkv, ckv, DOWN_, D_, 4 };
        jb.j[1] = { h, Wdq,  bdq,  cq,  DOWN_, D_, 4 };
        jb.j[2] = { h, WkrP, bkrP, krl, KRS,   D_, 1 };
        jb.j[3] = jb.j[2];
        gemm_batch<<<dim3(4, 32, 3), 256, GEMM_SMEM>>>(jb);
    }

    // stage 2: kc + vc + qc + qr
    {
        GJobs jb;
        jb.j[0] = { ckv, Wuk, buk, kc, UP_,     DOWN_, 8 };
        jb.j[1] = { ckv, Wuv, buv, vc, UP_,     DOWN_, 8 };
        jb.j[2] = { cq,  Wuq, buq, qc, UP_,     DOWN_, 8 };
        jb.j[3] = { cq,  Wqr, bqr, qr, RD_*H_,  DOWN_, 4 };
        gemm_batch<<<dim3(8, 32, 4), 256, GEMM_SMEM>>>(jb);
    }

    rope_kernel<<<MROWS, 256>>>(qr,  H_, RD_*H_);
    rope_kernel<<<MROWS, 32>>>(krl, 1,  KRS);

    attn_mma<<<dim3(S_/128, H_, BS_), 256, ATT_SMEM>>>(qc, qr, kc, krl, vc, ao);

    // output projection
    {
        GJobs jb;
        jb.j[0] = { ao, Wfc, bfc, out, D_, UP_, 16 };
        jb.j[1] = jb.j[0]; jb.j[2] = jb.j[0]; jb.j[3] = jb.j[0];
        gemm_batch<<<dim3(16, 32, 1), 256, GEMM_SMEM>>>(jb);
    }
}